// round 11
// baseline (speedup 1.0000x reference)
#include <cuda_runtime.h>
#include <cuda_bf16.h>
#include <stdint.h>
#include <math.h>

#define BATCH   2
#define SEQ     2048
#define EMB     1024
#define NHEAD   16
#define HDIM    64
#define MROWS   (BATCH * SEQ)
#define K3      (3 * EMB)
#define QKV_ELEMS (BATCH * NHEAD * SEQ * HDIM)

// Scratch (__device__ globals)
__device__ __nv_bfloat16 g_Qhi[QKV_ELEMS];
__device__ __nv_bfloat16 g_Qlo[QKV_ELEMS];
__device__ __nv_bfloat16 g_Khi[QKV_ELEMS];
__device__ __nv_bfloat16 g_Klo[QKV_ELEMS];
__device__ __nv_bfloat16 g_VThi[QKV_ELEMS];   // [B,H,D,S]
__device__ __nv_bfloat16 g_VTlo[QKV_ELEMS];
__device__ __nv_bfloat16 g_Xs[(size_t)MROWS * K3];
__device__ __nv_bfloat16 g_Ws[4][(size_t)EMB * K3];
__device__ __nv_bfloat16 g_As[(size_t)MROWS * K3];

// ---------------------------------------------------------------------------
__device__ __forceinline__ uint32_t smem_u32(const void* p) {
    uint32_t a;
    asm("{ .reg .u64 t; cvta.to.shared.u64 t, %1; cvt.u32.u64 %0, t; }" : "=r"(a) : "l"(p));
    return a;
}
#define CP_ASYNC16(dst, src) asm volatile("cp.async.cg.shared.global [%0], [%1], 16;" :: "r"(dst), "l"(src))
#define CP_COMMIT()  asm volatile("cp.async.commit_group;" ::: "memory")
#define CP_WAIT2()   asm volatile("cp.async.wait_group 2;" ::: "memory")
#define CP_WAIT1()   asm volatile("cp.async.wait_group 1;" ::: "memory")
#define CP_WAIT0()   asm volatile("cp.async.wait_group 0;" ::: "memory")

__device__ __forceinline__ void ldsm_x4(uint32_t& r0, uint32_t& r1, uint32_t& r2, uint32_t& r3,
                                        uint32_t addr)
{
    asm volatile("ldmatrix.sync.aligned.m8n8.x4.shared.b16 {%0,%1,%2,%3}, [%4];"
        : "=r"(r0), "=r"(r1), "=r"(r2), "=r"(r3) : "r"(addr));
}

__device__ __forceinline__ void hilo2(float x, float y, uint32_t& hi, uint32_t& lo)
{
    __nv_bfloat16 hx = __float2bfloat16(x), hy = __float2bfloat16(y);
    __nv_bfloat16 lx = __float2bfloat16(x - __bfloat162float(hx));
    __nv_bfloat16 ly = __float2bfloat16(y - __bfloat162float(hy));
    __nv_bfloat162 h2; h2.x = hx; h2.y = hy;
    __nv_bfloat162 l2; l2.x = lx; l2.y = ly;
    hi = *(uint32_t*)&h2;
    lo = *(uint32_t*)&l2;
}

__device__ __forceinline__ void hilo1(float x, __nv_bfloat16& h, __nv_bfloat16& l)
{
    h = __float2bfloat16(x);
    l = __float2bfloat16(x - __bfloat162float(h));
}

__device__ __forceinline__ void mma16816(float* c, const uint32_t* a, const uint32_t* b)
{
    asm volatile(
        "mma.sync.aligned.m16n8k16.row.col.f32.bf16.bf16.f32 "
        "{%0,%1,%2,%3}, {%4,%5,%6,%7}, {%8,%9}, {%0,%1,%2,%3};"
        : "+f"(c[0]), "+f"(c[1]), "+f"(c[2]), "+f"(c[3])
        : "r"(a[0]), "r"(a[1]), "r"(a[2]), "r"(a[3]), "r"(b[0]), "r"(b[1]));
}

// ---------------------------------------------------------------------------
// Split conversion kernels (vectorized: 4 elems/thread, 8B stores)
// ---------------------------------------------------------------------------
__device__ __forceinline__ uint2 pack4hi(float a, float b, float c, float d)
{
    __nv_bfloat162 p0; p0.x = __float2bfloat16(a); p0.y = __float2bfloat16(b);
    __nv_bfloat162 p1; p1.x = __float2bfloat16(c); p1.y = __float2bfloat16(d);
    uint2 r; r.x = *(uint32_t*)&p0; r.y = *(uint32_t*)&p1;
    return r;
}
__device__ __forceinline__ uint2 pack4lo(float a, float b, float c, float d)
{
    __nv_bfloat16 ha = __float2bfloat16(a), hb = __float2bfloat16(b);
    __nv_bfloat16 hc = __float2bfloat16(c), hd = __float2bfloat16(d);
    __nv_bfloat162 p0; p0.x = __float2bfloat16(a - __bfloat162float(ha));
    p0.y = __float2bfloat16(b - __bfloat162float(hb));
    __nv_bfloat162 p1; p1.x = __float2bfloat16(c - __bfloat162float(hc));
    p1.y = __float2bfloat16(d - __bfloat162float(hd));
    uint2 r; r.x = *(uint32_t*)&p0; r.y = *(uint32_t*)&p1;
    return r;
}

__global__ void split_x_kernel(const float* __restrict__ in,
                               __nv_bfloat16* __restrict__ out)
{
    int idx = (blockIdx.x * blockDim.x + threadIdx.x) * 4;
    int r = idx >> 10;
    int k = idx & 1023;
    float4 x = *(const float4*)(in + idx);
    uint2 hh = pack4hi(x.x, x.y, x.z, x.w);
    uint2 ll = pack4lo(x.x, x.y, x.z, x.w);
    __nv_bfloat16* o = out + (size_t)r * K3 + k;
    *(uint2*)(o)        = hh;
    *(uint2*)(o + 1024) = hh;
    *(uint2*)(o + 2048) = ll;
}

__global__ void split_w_kernel(const float* __restrict__ W0, const float* __restrict__ W1,
                               const float* __restrict__ W2, const float* __restrict__ W3,
                               __nv_bfloat16* __restrict__ out)
{
    int w = blockIdx.y;
    const float* in = (w == 0) ? W0 : (w == 1) ? W1 : (w == 2) ? W2 : W3;
    int idx = (blockIdx.x * blockDim.x + threadIdx.x) * 4;
    int r = idx >> 10;
    int k = idx & 1023;
    float4 x = *(const float4*)(in + idx);
    uint2 hh = pack4hi(x.x, x.y, x.z, x.w);
    uint2 ll = pack4lo(x.x, x.y, x.z, x.w);
    __nv_bfloat16* o = out + (size_t)w * EMB * K3 + (size_t)r * K3 + k;
    *(uint2*)(o)        = hh;
    *(uint2*)(o + 1024) = ll;
    *(uint2*)(o + 2048) = hh;
}

// ---------------------------------------------------------------------------
// bf16 HMMA GEMM (R9 shape, KCH=64): CTA 128x128, 8 warps (64x32 each),
// K=3072, 3-stage cp.async, ldmatrix. occ 2.
// mode 0: fused QKV; Q/K split [B,H,S,D], V split TRANSPOSED [B,H,D,S].
// mode 1: O-projection, fp32 row-major.
// ---------------------------------------------------------------------------
#define GPAD    72
#define KCH     64
#define NCHUNK  (K3 / KCH)                  // 48
#define A_STAGE (128 * GPAD * 2)            // 18432 B per array per stage
#define G_SMEM  (6 * A_STAGE)               // 110592 B

__global__ void __launch_bounds__(256, 2)
gemm_mma_kernel(const __nv_bfloat16* __restrict__ A,
                const __nv_bfloat16* __restrict__ B,
                const float* __restrict__ bias0, const float* __restrict__ bias1,
                const float* __restrict__ bias2,
                __nv_bfloat16* __restrict__ Qhi, __nv_bfloat16* __restrict__ Qlo,
                __nv_bfloat16* __restrict__ Khi, __nv_bfloat16* __restrict__ Klo,
                __nv_bfloat16* __restrict__ VThi, __nv_bfloat16* __restrict__ VTlo,
                float* __restrict__ Cf, int mode)
{
    extern __shared__ __nv_bfloat16 smraw[];

    const int tid  = threadIdx.x;
    const int wid  = tid >> 5;
    const int lane = tid & 31;
    const int g    = lane >> 2;
    const int t    = lane & 3;
    const int bm   = blockIdx.y;
    const int bn   = blockIdx.x;
    const int wm   = (wid >> 2) * 64;
    const int wn   = (wid & 3) * 32;

    const int arow = (lane & 7) + ((lane >> 3) & 1) * 8;
    const int acol = (lane >> 4) * 8;
    const int brow = (lane & 7) + ((lane >> 4) & 1) * 8;
    const int bcol = ((lane >> 3) & 1) * 8;

    const uint32_t aBase = smem_u32(smraw);            // As[3][128][GPAD]
    const uint32_t bBase = aBase + 3 * A_STAGE;        // Bs[3][128][GPAD]

    const int lrow = tid >> 1;          // 0..127
    const int lco  = (tid & 1) * 32;    // 0 or 32
    const __nv_bfloat16* Ag = A + (size_t)(bm * 128 + lrow) * K3 + lco;
    const __nv_bfloat16* Bg = B + (size_t)(bn * 128 + lrow) * K3 + lco;
    const uint32_t dA = aBase + ((uint32_t)lrow * GPAD + lco) * 2;
    const uint32_t dB = bBase + ((uint32_t)lrow * GPAD + lco) * 2;

    auto load_st = [&](int st, int k0) {
#pragma unroll
        for (int j = 0; j < 4; j++) {
            CP_ASYNC16(dA + st * A_STAGE + j * 16, Ag + k0 + j * 8);
            CP_ASYNC16(dB + st * A_STAGE + j * 16, Bg + k0 + j * 8);
        }
        CP_COMMIT();
    };

    float acc[4][4][4];
#pragma unroll
    for (int i = 0; i < 4; i++)
#pragma unroll
        for (int j = 0; j < 4; j++)
#pragma unroll
            for (int q = 0; q < 4; q++) acc[i][j][q] = 0.f;

    load_st(0, 0);
    load_st(1, KCH);

    for (int c = 0; c < NCHUNK; c++) {
        const int st = c % 3;
        if (c + 2 < NCHUNK) { load_st((c + 2) % 3, (c + 2) * KCH); CP_WAIT2(); }
        else if (c + 1 < NCHUNK) { CP_WAIT1(); }
        else { CP_WAIT0(); }
        __syncthreads();

        const uint32_t aS = aBase + st * A_STAGE;
        const uint32_t bS = bBase + st * A_STAGE;

#pragma unroll
        for (int kk = 0; kk < KCH; kk += 16) {
            uint32_t af[4][4], bf[4][2];
#pragma unroll
            for (int mi = 0; mi < 4; mi++) {
                uint32_t addr = aS + (((uint32_t)(wm + mi * 16 + arow)) * GPAD + kk + acol) * 2;
                ldsm_x4(af[mi][0], af[mi][1], af[mi][2], af[mi][3], addr);
            }
#pragma unroll
            for (int np = 0; np < 2; np++) {
                uint32_t addr = bS + (((uint32_t)(wn + np * 16 + brow)) * GPAD + kk + bcol) * 2;
                ldsm_x4(bf[2 * np][0], bf[2 * np][1], bf[2 * np + 1][0], bf[2 * np + 1][1], addr);
            }
#pragma unroll
            for (int mi = 0; mi < 4; mi++)
#pragma unroll
                for (int ni = 0; ni < 4; ni++)
                    mma16816(acc[mi][ni], af[mi], bf[ni]);
        }
        __syncthreads();
    }

    // epilogue
#pragma unroll
    for (int mi = 0; mi < 4; mi++) {
        const int r0 = bm * 128 + wm + mi * 16 + g;
#pragma unroll
        for (int ni = 0; ni < 4; ni++) {
            const int c = bn * 128 + wn + ni * 8 + 2 * t;
            if (mode == 0) {
                const int which = c >> 10;
                const int cc    = c & 1023;
                const float* bp = (which == 0) ? bias0 : (which == 1) ? bias1 : bias2;
                const float bv0 = bp[cc], bv1 = bp[cc + 1];
                float v00 = acc[mi][ni][0] + bv0, v01 = acc[mi][ni][1] + bv1;
                float v10 = acc[mi][ni][2] + bv0, v11 = acc[mi][ni][3] + bv1;
                const int b = r0 >> 11, sq = r0 & 2047;
                const int h = cc >> 6, d = cc & 63;
                if (which < 2) {
                    size_t off0 = (((size_t)(b * NHEAD + h) * SEQ) + sq) * HDIM + d;
                    size_t off1 = off0 + 8 * HDIM;
                    __nv_bfloat16* Hh = (which == 0) ? Qhi : Khi;
                    __nv_bfloat16* Ll = (which == 0) ? Qlo : Klo;
                    uint32_t hi0, lo0, hi1, lo1;
                    hilo2(v00, v01, hi0, lo0);
                    hilo2(v10, v11, hi1, lo1);
                    *(uint32_t*)(Hh + off0) = hi0;
                    *(uint32_t*)(Ll + off0) = lo0;
                    *(uint32_t*)(Hh + off1) = hi1;
                    *(uint32_t*)(Ll + off1) = lo1;
                } else {
                    size_t offT = (((size_t)(b * NHEAD + h) * HDIM) + d) * SEQ + sq;
                    __nv_bfloat16 h00, l00, h01, l01, h10, l10, h11, l11;
                    hilo1(v00, h00, l00);
                    hilo1(v01, h01, l01);
                    hilo1(v10, h10, l10);
                    hilo1(v11, h11, l11);
                    VThi[offT]           = h00;
                    VThi[offT + 8]       = h10;
                    VThi[offT + SEQ]     = h01;
                    VThi[offT + SEQ + 8] = h11;
                    VTlo[offT]           = l00;
                    VTlo[offT + 8]       = l10;
                    VTlo[offT + SEQ]     = l01;
                    VTlo[offT + SEQ + 8] = l11;
                }
            } else {
                const float bv0 = bias0[c], bv1 = bias0[c + 1];
                *(float2*)(Cf + (size_t)r0 * EMB + c) =
                    make_float2(acc[mi][ni][0] + bv0, acc[mi][ni][1] + bv1);
                *(float2*)(Cf + (size_t)(r0 + 8) * EMB + c) =
                    make_float2(acc[mi][ni][2] + bv0, acc[mi][ni][3] + bv1);
            }
        }
    }
}

// ---------------------------------------------------------------------------
// Tensor-core flash attention (R9-exact): Br=64, cp.async double-buffer,
// ldmatrix frags, occ 3. grid (SEQ/64, B*H), block 128.
// ---------------------------------------------------------------------------
#define ASTR 72
#define A_STG (64 * ASTR)
#define ATT_SMEM (8 * A_STG * 2)

__global__ void __launch_bounds__(128, 3)
attn_mma_kernel(const __nv_bfloat16* __restrict__ Qhi, const __nv_bfloat16* __restrict__ Qlo,
                const __nv_bfloat16* __restrict__ Khi, const __nv_bfloat16* __restrict__ Klo,
                const __nv_bfloat16* __restrict__ VThi, const __nv_bfloat16* __restrict__ VTlo,
                __nv_bfloat16* __restrict__ Out)
{
    extern __shared__ __nv_bfloat16 sm[];
    __nv_bfloat16* sK  = sm;
    __nv_bfloat16* sVT = sm + 4 * A_STG;

    const int tid  = threadIdx.x;
    const int wid  = tid >> 5;
    const int lane = tid & 31;
    const int g    = lane >> 2;
    const int t    = lane & 3;
    const int qt   = blockIdx.x;
    const int bh   = blockIdx.y;
    const size_t base  = (size_t)bh * SEQ * HDIM;
    const size_t baseT = (size_t)bh * HDIM * SEQ;

    const int brow = (lane & 7) + ((lane >> 4) & 1) * 8;
    const int bcol = ((lane >> 3) & 1) * 8;

    // --- Stage Q tile into sK stage 0, extract frags ---
#pragma unroll
    for (int i = 0; i < 4; i++) {
        int idx = tid + 128 * i;
        int row = idx >> 3;
        int co  = (idx & 7) * 8;
        *(uint4*)&sK[row * ASTR + co]         = *(const uint4*)&Qhi[base + (size_t)(qt * 64 + row) * HDIM + co];
        *(uint4*)&sK[A_STG + row * ASTR + co] = *(const uint4*)&Qlo[base + (size_t)(qt * 64 + row) * HDIM + co];
    }
    __syncthreads();

    uint32_t qh[4][4], ql[4][4];
    {
        const int arow = (lane & 7) + ((lane >> 3) & 1) * 8;
        const int acol = (lane >> 4) * 8;
        const uint32_t qBase = smem_u32(sK);
#pragma unroll
        for (int kj = 0; kj < 4; kj++) {
            uint32_t ah = qBase + (((uint32_t)(wid * 16 + arow)) * ASTR + 16 * kj + acol) * 2;
            ldsm_x4(qh[kj][0], qh[kj][1], qh[kj][2], qh[kj][3], ah);
            ldsm_x4(ql[kj][0], ql[kj][1], ql[kj][2], ql[kj][3], ah + A_STG * 2);
        }
    }
    __syncthreads();

    const uint32_t sKa  = smem_u32(sK);
    const uint32_t sVTa = smem_u32(sVT);
    auto stage = [&](int st, int kt) {
#pragma unroll
        for (int j = 0; j < 4; j++) {
            int id  = tid + 128 * j;
            int row = id >> 3;
            int co  = (id & 7) * 8;
            uint32_t so = ((uint32_t)row * ASTR + co) * 2;
            CP_ASYNC16(sKa  + (st * 2 + 0) * A_STG * 2 + so, Khi  + base  + (size_t)(kt + row) * HDIM + co);
            CP_ASYNC16(sKa  + (st * 2 + 1) * A_STG * 2 + so, Klo  + base  + (size_t)(kt + row) * HDIM + co);
            CP_ASYNC16(sVTa + (st * 2 + 0) * A_STG * 2 + so, VThi + baseT + (size_t)row * SEQ + kt + co);
            CP_ASYNC16(sVTa + (st * 2 + 1) * A_STG * 2 + so, VTlo + baseT + (size_t)row * SEQ + kt + co);
        }
        CP_COMMIT();
    };

    float o[8][4];
#pragma unroll
    for (int ni = 0; ni < 8; ni++)
#pragma unroll
        for (int j = 0; j < 4; j++) o[ni][j] = 0.f;
    float m0 = -1e30f, m1 = -1e30f, l0 = 0.f, l1 = 0.f;

    stage(0, 0);
    stage(1, 64);

    const int NT = SEQ / 64;
    for (int it = 0; it < NT; it++) {
        const int s = it & 1;
        if (it + 1 < NT) { CP_WAIT1(); } else { CP_WAIT0(); }
        __syncthreads();

        const uint32_t cKhiA = sKa  + (s * 2 + 0) * A_STG * 2;
        const uint32_t cKloA = sKa  + (s * 2 + 1) * A_STG * 2;
        const uint32_t cVhiA = sVTa + (s * 2 + 0) * A_STG * 2;
        const uint32_t cVloA = sVTa + (s * 2 + 1) * A_STG * 2;
        const uint32_t bOff  = ((uint32_t)brow * ASTR + bcol) * 2;

        // --- S = Q K^T (3 split terms) ---
        float sc[8][4];
#pragma unroll
        for (int ni = 0; ni < 8; ni++)
#pragma unroll
            for (int j = 0; j < 4; j++) sc[ni][j] = 0.f;

#pragma unroll
        for (int kj = 0; kj < 4; kj++) {
#pragma unroll
            for (int np = 0; np < 4; np++) {
                uint32_t off = bOff + ((uint32_t)np * 16 * ASTR + 16 * kj) * 2;
                uint32_t h0[2], h1[2], l0_[2], l1_[2];
                ldsm_x4(h0[0], h0[1], h1[0], h1[1], cKhiA + off);
                ldsm_x4(l0_[0], l0_[1], l1_[0], l1_[1], cKloA + off);
                mma16816(sc[2 * np],     qh[kj], h0);
                mma16816(sc[2 * np],     qh[kj], l0_);
                mma16816(sc[2 * np],     ql[kj], h0);
                mma16816(sc[2 * np + 1], qh[kj], h1);
                mma16816(sc[2 * np + 1], qh[kj], l1_);
                mma16816(sc[2 * np + 1], ql[kj], h1);
            }
        }

        // --- online softmax ---
        float mx0 = -1e30f, mx1 = -1e30f;
#pragma unroll
        for (int ni = 0; ni < 8; ni++) {
            sc[ni][0] *= 0.125f; sc[ni][1] *= 0.125f;
            sc[ni][2] *= 0.125f; sc[ni][3] *= 0.125f;
            mx0 = fmaxf(mx0, fmaxf(sc[ni][0], sc[ni][1]));
            mx1 = fmaxf(mx1, fmaxf(sc[ni][2], sc[ni][3]));
        }
        mx0 = fmaxf(mx0, __shfl_xor_sync(0xffffffff, mx0, 1));
        mx0 = fmaxf(mx0, __shfl_xor_sync(0xffffffff, mx0, 2));
        mx1 = fmaxf(mx1, __shfl_xor_sync(0xffffffff, mx1, 1));
        mx1 = fmaxf(mx1, __shfl_xor_sync(0xffffffff, mx1, 2));

        const float nm0 = fmaxf(m0, mx0);
        const float nm1 = fmaxf(m1, mx1);
        const float rs0 = __expf(m0 - nm0);
        const float rs1 = __expf(m1 - nm1);
        m0 = nm0; m1 = nm1;
        l0 *= rs0; l1 *= rs1;
#pragma unroll
        for (int ni = 0; ni < 8; ni++) {
            o[ni][0] *= rs0; o[ni][1] *= rs0;
            o[ni][2] *= rs1; o[ni][3] *= rs1;
            sc[ni][0] = __expf(sc[ni][0] - m0);
            sc[ni][1] = __expf(sc[ni][1] - m0);
            sc[ni][2] = __expf(sc[ni][2] - m1);
            sc[ni][3] = __expf(sc[ni][3] - m1);
            l0 += sc[ni][0] + sc[ni][1];
            l1 += sc[ni][2] + sc[ni][3];
        }

        // --- O += P V (3 split terms) ---
#pragma unroll
        for (int kj = 0; kj < 4; kj++) {
            uint32_t ah[4], al[4];
            hilo2(sc[2 * kj][0],     sc[2 * kj][1],     ah[0], al[0]);
            hilo2(sc[2 * kj][2],     sc[2 * kj][3],     ah[1], al[1]);
            hilo2(sc[2 * kj + 1][0], sc[2 * kj + 1][1], ah[2], al[2]);
            hilo2(sc[2 * kj + 1][2], sc[2 * kj + 1][3], ah[3], al[3]);
#pragma unroll
            for (int np = 0; np < 4; np++) {
                uint32_t off = bOff + ((uint32_t)np * 16 * ASTR + 16 * kj) * 2;
                uint32_t h0[2], h1[2], l0_[2], l1_[2];
                ldsm_x4(h0[0], h0[1], h1[0], h1[1], cVhiA + off);
                ldsm_x4(l0_[0], l0_[1], l1_[0], l1_[1], cVloA + off);
                mma16816(o[2 * np],     ah, h0);
                mma16816(o[2 * np],     ah, l0_);
                mma16816(o[2 * np],     al, h0);
                mma16816(o[2 * np + 1], ah, h1);
                mma16816(o[2 * np + 1], ah, l1_);
                mma16816(o[2 * np + 1], al, h1);
            }
        }

        __syncthreads();
        if (it + 2 < NT) stage(s, (it + 2) * 64);
    }

    // --- finalize ---
    l0 += __shfl_xor_sync(0xffffffff, l0, 1);
    l0 += __shfl_xor_sync(0xffffffff, l0, 2);
    l1 += __shfl_xor_sync(0xffffffff, l1, 1);
    l1 += __shfl_xor_sync(0xffffffff, l1, 2);
    const float inv0 = 1.f / l0;
    const float inv1 = 1.f / l1;

    const int s0 = qt * 64 + wid * 16 + g;
    const int b  = bh >> 4;
    const int h  = bh & 15;
    const size_t row0 = (size_t)(b * SEQ + s0) * K3;
    const size_t row1 = row0 + (size_t)8 * K3;

#pragma unroll
    for (int ni = 0; ni < 8; ni++) {
        const int col = h * 64 + 8 * ni + 2 * t;
        uint32_t hi0, lo0, hi1, lo1;
        hilo2(o[ni][0] * inv0, o[ni][1] * inv0, hi0, lo0);
        hilo2(o[ni][2] * inv1, o[ni][3] * inv1, hi1, lo1);
        *(uint32_t*)&Out[row0 + col]        = hi0;
        *(uint32_t*)&Out[row0 + col + 1024] = hi0;
        *(uint32_t*)&Out[row0 + col + 2048] = lo0;
        *(uint32_t*)&Out[row1 + col]        = hi1;
        *(uint32_t*)&Out[row1 + col + 1024] = hi1;
        *(uint32_t*)&Out[row1 + col + 2048] = lo1;
    }
}

// ---------------------------------------------------------------------------
extern "C" void kernel_launch(void* const* d_in, const int* in_sizes, int n_in,
                              void* d_out, int out_size)
{
    const float* X   = (const float*)d_in[0];
    const float* W_q = (const float*)d_in[1];
    const float* b_q = (const float*)d_in[2];
    const float* W_k = (const float*)d_in[3];
    const float* b_k = (const float*)d_in[4];
    const float* W_v = (const float*)d_in[5];
    const float* b_v = (const float*)d_in[6];
    const float* W_o = (const float*)d_in[7];
    const float* b_o = (const float*)d_in[8];
    float* out = (float*)d_out;

    __nv_bfloat16 *Qhi, *Qlo, *Khi, *Klo, *VThi, *VTlo, *Xs, *Ws, *As;
    cudaGetSymbolAddress((void**)&Qhi, g_Qhi);
    cudaGetSymbolAddress((void**)&Qlo, g_Qlo);
    cudaGetSymbolAddress((void**)&Khi, g_Khi);
    cudaGetSymbolAddress((void**)&Klo, g_Klo);
    cudaGetSymbolAddress((void**)&VThi, g_VThi);
    cudaGetSymbolAddress((void**)&VTlo, g_VTlo);
    cudaGetSymbolAddress((void**)&Xs, g_Xs);
    cudaGetSymbolAddress((void**)&Ws, g_Ws);
    cudaGetSymbolAddress((void**)&As, g_As);

    cudaFuncSetAttribute(gemm_mma_kernel, cudaFuncAttributeMaxDynamicSharedMemorySize, G_SMEM);
    cudaFuncSetAttribute(attn_mma_kernel, cudaFuncAttributeMaxDynamicSharedMemorySize, ATT_SMEM);

    const int cthr = 256;
    split_x_kernel<<<MROWS * EMB / (cthr * 4), cthr>>>(X, Xs);
    dim3 wgrid(EMB * EMB / (cthr * 4), 4);
    split_w_kernel<<<wgrid, cthr>>>(W_q, W_k, W_v, W_o, Ws);

    // fused QKV (V written pre-transposed): N = 3072, tile 128x128
    dim3 qkvgrid(K3 / 128, MROWS / 128);   // (24, 32)
    gemm_mma_kernel<<<qkvgrid, 256, G_SMEM>>>(Xs, Ws, b_q, b_k, b_v,
                                              Qhi, Qlo, Khi, Klo, VThi, VTlo, nullptr, 0);

    dim3 agrid(SEQ / 64, BATCH * NHEAD);
    attn_mma_kernel<<<agrid, 128, ATT_SMEM>>>(Qhi, Qlo, Khi, Klo, VThi, VTlo, As);

    // O-projection: N = 1024
    dim3 ogrid(EMB / 128, MROWS / 128);    // (8, 32)
    gemm_mma_kernel<<<ogrid, 256, G_SMEM>>>(As, Ws + 3 * (size_t)EMB * K3, b_o, nullptr, nullptr,
                                            nullptr, nullptr, nullptr, nullptr, nullptr, nullptr,
                                            out, 1);
}

// round 12
// speedup vs baseline: 1.0798x; 1.0798x over previous
#include <cuda_runtime.h>
#include <cuda_bf16.h>
#include <stdint.h>
#include <math.h>

#define BATCH   2
#define SEQ     2048
#define EMB     1024
#define NHEAD   16
#define HDIM    64
#define MROWS   (BATCH * SEQ)
#define K3      (3 * EMB)
#define QKV_ELEMS (BATCH * NHEAD * SEQ * HDIM)

// Scratch (__device__ globals)
__device__ __nv_bfloat16 g_Qhi[QKV_ELEMS];
__device__ __nv_bfloat16 g_Qlo[QKV_ELEMS];
__device__ __nv_bfloat16 g_Khi[QKV_ELEMS];
__device__ __nv_bfloat16 g_Klo[QKV_ELEMS];
__device__ __nv_bfloat16 g_VThi[QKV_ELEMS];   // [B,H,D,S]
__device__ __nv_bfloat16 g_VTlo[QKV_ELEMS];
__device__ __nv_bfloat16 g_Xs[(size_t)MROWS * K3];
__device__ __nv_bfloat16 g_Ws[4][(size_t)EMB * K3];
__device__ __nv_bfloat16 g_As[(size_t)MROWS * K3];

// ---------------------------------------------------------------------------
__device__ __forceinline__ uint32_t smem_u32(const void* p) {
    uint32_t a;
    asm("{ .reg .u64 t; cvta.to.shared.u64 t, %1; cvt.u32.u64 %0, t; }" : "=r"(a) : "l"(p));
    return a;
}
#define CP_ASYNC16(dst, src) asm volatile("cp.async.cg.shared.global [%0], [%1], 16;" :: "r"(dst), "l"(src))
#define CP_COMMIT()  asm volatile("cp.async.commit_group;" ::: "memory")
#define CP_WAIT2()   asm volatile("cp.async.wait_group 2;" ::: "memory")
#define CP_WAIT1()   asm volatile("cp.async.wait_group 1;" ::: "memory")
#define CP_WAIT0()   asm volatile("cp.async.wait_group 0;" ::: "memory")

__device__ __forceinline__ void ldsm_x4(uint32_t& r0, uint32_t& r1, uint32_t& r2, uint32_t& r3,
                                        uint32_t addr)
{
    asm volatile("ldmatrix.sync.aligned.m8n8.x4.shared.b16 {%0,%1,%2,%3}, [%4];"
        : "=r"(r0), "=r"(r1), "=r"(r2), "=r"(r3) : "r"(addr));
}

__device__ __forceinline__ void hilo2(float x, float y, uint32_t& hi, uint32_t& lo)
{
    __nv_bfloat16 hx = __float2bfloat16(x), hy = __float2bfloat16(y);
    __nv_bfloat16 lx = __float2bfloat16(x - __bfloat162float(hx));
    __nv_bfloat16 ly = __float2bfloat16(y - __bfloat162float(hy));
    __nv_bfloat162 h2; h2.x = hx; h2.y = hy;
    __nv_bfloat162 l2; l2.x = lx; l2.y = ly;
    hi = *(uint32_t*)&h2;
    lo = *(uint32_t*)&l2;
}

__device__ __forceinline__ void hilo1(float x, __nv_bfloat16& h, __nv_bfloat16& l)
{
    h = __float2bfloat16(x);
    l = __float2bfloat16(x - __bfloat162float(h));
}

__device__ __forceinline__ void mma16816(float* c, const uint32_t* a, const uint32_t* b)
{
    asm volatile(
        "mma.sync.aligned.m16n8k16.row.col.f32.bf16.bf16.f32 "
        "{%0,%1,%2,%3}, {%4,%5,%6,%7}, {%8,%9}, {%0,%1,%2,%3};"
        : "+f"(c[0]), "+f"(c[1]), "+f"(c[2]), "+f"(c[3])
        : "r"(a[0]), "r"(a[1]), "r"(a[2]), "r"(a[3]), "r"(b[0]), "r"(b[1]));
}

// ---------------------------------------------------------------------------
// Split conversion kernels (vectorized: 4 elems/thread, 8B stores)
// ---------------------------------------------------------------------------
__device__ __forceinline__ uint2 pack4hi(float a, float b, float c, float d)
{
    __nv_bfloat162 p0; p0.x = __float2bfloat16(a); p0.y = __float2bfloat16(b);
    __nv_bfloat162 p1; p1.x = __float2bfloat16(c); p1.y = __float2bfloat16(d);
    uint2 r; r.x = *(uint32_t*)&p0; r.y = *(uint32_t*)&p1;
    return r;
}
__device__ __forceinline__ uint2 pack4lo(float a, float b, float c, float d)
{
    __nv_bfloat16 ha = __float2bfloat16(a), hb = __float2bfloat16(b);
    __nv_bfloat16 hc = __float2bfloat16(c), hd = __float2bfloat16(d);
    __nv_bfloat162 p0; p0.x = __float2bfloat16(a - __bfloat162float(ha));
    p0.y = __float2bfloat16(b - __bfloat162float(hb));
    __nv_bfloat162 p1; p1.x = __float2bfloat16(c - __bfloat162float(hc));
    p1.y = __float2bfloat16(d - __bfloat162float(hd));
    uint2 r; r.x = *(uint32_t*)&p0; r.y = *(uint32_t*)&p1;
    return r;
}

__global__ void split_x_kernel(const float* __restrict__ in,
                               __nv_bfloat16* __restrict__ out)
{
    int idx = (blockIdx.x * blockDim.x + threadIdx.x) * 4;
    int r = idx >> 10;
    int k = idx & 1023;
    float4 x = *(const float4*)(in + idx);
    uint2 hh = pack4hi(x.x, x.y, x.z, x.w);
    uint2 ll = pack4lo(x.x, x.y, x.z, x.w);
    __nv_bfloat16* o = out + (size_t)r * K3 + k;
    *(uint2*)(o)        = hh;
    *(uint2*)(o + 1024) = hh;
    *(uint2*)(o + 2048) = ll;
}

__global__ void split_w_kernel(const float* __restrict__ W0, const float* __restrict__ W1,
                               const float* __restrict__ W2, const float* __restrict__ W3,
                               __nv_bfloat16* __restrict__ out)
{
    int w = blockIdx.y;
    const float* in = (w == 0) ? W0 : (w == 1) ? W1 : (w == 2) ? W2 : W3;
    int idx = (blockIdx.x * blockDim.x + threadIdx.x) * 4;
    int r = idx >> 10;
    int k = idx & 1023;
    float4 x = *(const float4*)(in + idx);
    uint2 hh = pack4hi(x.x, x.y, x.z, x.w);
    uint2 ll = pack4lo(x.x, x.y, x.z, x.w);
    __nv_bfloat16* o = out + (size_t)w * EMB * K3 + (size_t)r * K3 + k;
    *(uint2*)(o)        = hh;
    *(uint2*)(o + 1024) = ll;
    *(uint2*)(o + 2048) = hh;
}

// ---------------------------------------------------------------------------
// bf16 HMMA GEMM (R9-exact): CTA 128x128, 8 warps (64x32), K=3072, KCH=32,
// GPAD=40, 3-stage cp.async, ldmatrix, occ 2.
// mode 0: fused QKV; Q/K split [B,H,S,D], V split TRANSPOSED [B,H,D,S].
// mode 1: O-projection, fp32 row-major.
// ---------------------------------------------------------------------------
#define GPAD   40
#define KCH    32
#define NCHUNK (K3 / KCH)
#define G_SMEM (2 * 3 * 128 * GPAD * 2)

__global__ void __launch_bounds__(256, 2)
gemm_mma_kernel(const __nv_bfloat16* __restrict__ A,
                const __nv_bfloat16* __restrict__ B,
                const float* __restrict__ bias0, const float* __restrict__ bias1,
                const float* __restrict__ bias2,
                __nv_bfloat16* __restrict__ Qhi, __nv_bfloat16* __restrict__ Qlo,
                __nv_bfloat16* __restrict__ Khi, __nv_bfloat16* __restrict__ Klo,
                __nv_bfloat16* __restrict__ VThi, __nv_bfloat16* __restrict__ VTlo,
                float* __restrict__ Cf, int mode)
{
    extern __shared__ __nv_bfloat16 smraw[];
    __nv_bfloat16 (*As)[128][GPAD] = reinterpret_cast<__nv_bfloat16(*)[128][GPAD]>(smraw);
    __nv_bfloat16 (*Bs)[128][GPAD] = reinterpret_cast<__nv_bfloat16(*)[128][GPAD]>(smraw + 3 * 128 * GPAD);

    const int tid  = threadIdx.x;
    const int wid  = tid >> 5;
    const int lane = tid & 31;
    const int g    = lane >> 2;
    const int t    = lane & 3;
    const int bm   = blockIdx.y;
    const int bn   = blockIdx.x;
    const int wm   = (wid >> 2) * 64;
    const int wn   = (wid & 3) * 32;

    const int arow = (lane & 7) + ((lane >> 3) & 1) * 8;
    const int acol = (lane >> 4) * 8;
    const int brow = (lane & 7) + ((lane >> 4) & 1) * 8;
    const int bcol = ((lane >> 3) & 1) * 8;

    const int lrow = tid >> 1;
    const int lco  = (tid & 1) * 16;
    const __nv_bfloat16* Ag = A + (size_t)(bm * 128 + lrow) * K3 + lco;
    const __nv_bfloat16* Bg = B + (size_t)(bn * 128 + lrow) * K3 + lco;
    const uint32_t dA = smem_u32(&As[0][lrow][lco]);
    const uint32_t dB = smem_u32(&Bs[0][lrow][lco]);
    const uint32_t stg_bytes = 128 * GPAD * 2;

    const uint32_t aBase = smem_u32(&As[0][0][0]);
    const uint32_t bBase = smem_u32(&Bs[0][0][0]);

    auto load_st = [&](int st, int k0) {
        CP_ASYNC16(dA + st * stg_bytes,      Ag + k0);
        CP_ASYNC16(dA + st * stg_bytes + 16, Ag + k0 + 8);
        CP_ASYNC16(dB + st * stg_bytes,      Bg + k0);
        CP_ASYNC16(dB + st * stg_bytes + 16, Bg + k0 + 8);
        CP_COMMIT();
    };

    float acc[4][4][4];
#pragma unroll
    for (int i = 0; i < 4; i++)
#pragma unroll
        for (int j = 0; j < 4; j++)
#pragma unroll
            for (int q = 0; q < 4; q++) acc[i][j][q] = 0.f;

    load_st(0, 0);
    load_st(1, KCH);

    for (int c = 0; c < NCHUNK; c++) {
        const int st = c % 3;
        if (c + 2 < NCHUNK) { load_st((c + 2) % 3, (c + 2) * KCH); CP_WAIT2(); }
        else if (c + 1 < NCHUNK) { CP_WAIT1(); }
        else { CP_WAIT0(); }
        __syncthreads();

        const uint32_t aS = aBase + st * stg_bytes;
        const uint32_t bS = bBase + st * stg_bytes;

#pragma unroll
        for (int kk = 0; kk < KCH; kk += 16) {
            uint32_t af[4][4], bf[4][2];
#pragma unroll
            for (int mi = 0; mi < 4; mi++) {
                uint32_t addr = aS + (((uint32_t)(wm + mi * 16 + arow)) * GPAD + kk + acol) * 2;
                ldsm_x4(af[mi][0], af[mi][1], af[mi][2], af[mi][3], addr);
            }
#pragma unroll
            for (int np = 0; np < 2; np++) {
                uint32_t addr = bS + (((uint32_t)(wn + np * 16 + brow)) * GPAD + kk + bcol) * 2;
                ldsm_x4(bf[2 * np][0], bf[2 * np][1], bf[2 * np + 1][0], bf[2 * np + 1][1], addr);
            }
#pragma unroll
            for (int mi = 0; mi < 4; mi++)
#pragma unroll
                for (int ni = 0; ni < 4; ni++)
                    mma16816(acc[mi][ni], af[mi], bf[ni]);
        }
        __syncthreads();
    }

    // epilogue
#pragma unroll
    for (int mi = 0; mi < 4; mi++) {
        const int r0 = bm * 128 + wm + mi * 16 + g;
#pragma unroll
        for (int ni = 0; ni < 4; ni++) {
            const int c = bn * 128 + wn + ni * 8 + 2 * t;
            if (mode == 0) {
                const int which = c >> 10;
                const int cc    = c & 1023;
                const float* bp = (which == 0) ? bias0 : (which == 1) ? bias1 : bias2;
                const float bv0 = bp[cc], bv1 = bp[cc + 1];
                float v00 = acc[mi][ni][0] + bv0, v01 = acc[mi][ni][1] + bv1;
                float v10 = acc[mi][ni][2] + bv0, v11 = acc[mi][ni][3] + bv1;
                const int b = r0 >> 11, sq = r0 & 2047;
                const int h = cc >> 6, d = cc & 63;
                if (which < 2) {
                    size_t off0 = (((size_t)(b * NHEAD + h) * SEQ) + sq) * HDIM + d;
                    size_t off1 = off0 + 8 * HDIM;
                    __nv_bfloat16* Hh = (which == 0) ? Qhi : Khi;
                    __nv_bfloat16* Ll = (which == 0) ? Qlo : Klo;
                    uint32_t hi0, lo0, hi1, lo1;
                    hilo2(v00, v01, hi0, lo0);
                    hilo2(v10, v11, hi1, lo1);
                    *(uint32_t*)(Hh + off0) = hi0;
                    *(uint32_t*)(Ll + off0) = lo0;
                    *(uint32_t*)(Hh + off1) = hi1;
                    *(uint32_t*)(Ll + off1) = lo1;
                } else {
                    size_t offT = (((size_t)(b * NHEAD + h) * HDIM) + d) * SEQ + sq;
                    __nv_bfloat16 h00, l00, h01, l01, h10, l10, h11, l11;
                    hilo1(v00, h00, l00);
                    hilo1(v01, h01, l01);
                    hilo1(v10, h10, l10);
                    hilo1(v11, h11, l11);
                    VThi[offT]           = h00;
                    VThi[offT + 8]       = h10;
                    VThi[offT + SEQ]     = h01;
                    VThi[offT + SEQ + 8] = h11;
                    VTlo[offT]           = l00;
                    VTlo[offT + 8]       = l10;
                    VTlo[offT + SEQ]     = l01;
                    VTlo[offT + SEQ + 8] = l11;
                }
            } else {
                const float bv0 = bias0[c], bv1 = bias0[c + 1];
                *(float2*)(Cf + (size_t)r0 * EMB + c) =
                    make_float2(acc[mi][ni][0] + bv0, acc[mi][ni][1] + bv1);
                *(float2*)(Cf + (size_t)(r0 + 8) * EMB + c) =
                    make_float2(acc[mi][ni][2] + bv0, acc[mi][ni][3] + bv1);
            }
        }
    }
}

// ---------------------------------------------------------------------------
// Tensor-core flash attention (R9-exact): Br=64, cp.async double-buffer,
// ldmatrix frags, occ 3. grid (SEQ/64, B*H), block 128.
// ---------------------------------------------------------------------------
#define ASTR 72
#define A_STG (64 * ASTR)
#define ATT_SMEM (8 * A_STG * 2)

__global__ void __launch_bounds__(128, 3)
attn_mma_kernel(const __nv_bfloat16* __restrict__ Qhi, const __nv_bfloat16* __restrict__ Qlo,
                const __nv_bfloat16* __restrict__ Khi, const __nv_bfloat16* __restrict__ Klo,
                const __nv_bfloat16* __restrict__ VThi, const __nv_bfloat16* __restrict__ VTlo,
                __nv_bfloat16* __restrict__ Out)
{
    extern __shared__ __nv_bfloat16 sm[];
    __nv_bfloat16* sK  = sm;
    __nv_bfloat16* sVT = sm + 4 * A_STG;

    const int tid  = threadIdx.x;
    const int wid  = tid >> 5;
    const int lane = tid & 31;
    const int g    = lane >> 2;
    const int t    = lane & 3;
    const int qt   = blockIdx.x;
    const int bh   = blockIdx.y;
    const size_t base  = (size_t)bh * SEQ * HDIM;
    const size_t baseT = (size_t)bh * HDIM * SEQ;

    const int brow = (lane & 7) + ((lane >> 4) & 1) * 8;
    const int bcol = ((lane >> 3) & 1) * 8;

    // --- Stage Q tile into sK stage 0, extract frags ---
#pragma unroll
    for (int i = 0; i < 4; i++) {
        int idx = tid + 128 * i;
        int row = idx >> 3;
        int co  = (idx & 7) * 8;
        *(uint4*)&sK[row * ASTR + co]         = *(const uint4*)&Qhi[base + (size_t)(qt * 64 + row) * HDIM + co];
        *(uint4*)&sK[A_STG + row * ASTR + co] = *(const uint4*)&Qlo[base + (size_t)(qt * 64 + row) * HDIM + co];
    }
    __syncthreads();

    uint32_t qh[4][4], ql[4][4];
    {
        const int arow = (lane & 7) + ((lane >> 3) & 1) * 8;
        const int acol = (lane >> 4) * 8;
        const uint32_t qBase = smem_u32(sK);
#pragma unroll
        for (int kj = 0; kj < 4; kj++) {
            uint32_t ah = qBase + (((uint32_t)(wid * 16 + arow)) * ASTR + 16 * kj + acol) * 2;
            ldsm_x4(qh[kj][0], qh[kj][1], qh[kj][2], qh[kj][3], ah);
            ldsm_x4(ql[kj][0], ql[kj][1], ql[kj][2], ql[kj][3], ah + A_STG * 2);
        }
    }
    __syncthreads();

    const uint32_t sKa  = smem_u32(sK);
    const uint32_t sVTa = smem_u32(sVT);
    auto stage = [&](int st, int kt) {
#pragma unroll
        for (int j = 0; j < 4; j++) {
            int id  = tid + 128 * j;
            int row = id >> 3;
            int co  = (id & 7) * 8;
            uint32_t so = ((uint32_t)row * ASTR + co) * 2;
            CP_ASYNC16(sKa  + (st * 2 + 0) * A_STG * 2 + so, Khi  + base  + (size_t)(kt + row) * HDIM + co);
            CP_ASYNC16(sKa  + (st * 2 + 1) * A_STG * 2 + so, Klo  + base  + (size_t)(kt + row) * HDIM + co);
            CP_ASYNC16(sVTa + (st * 2 + 0) * A_STG * 2 + so, VThi + baseT + (size_t)row * SEQ + kt + co);
            CP_ASYNC16(sVTa + (st * 2 + 1) * A_STG * 2 + so, VTlo + baseT + (size_t)row * SEQ + kt + co);
        }
        CP_COMMIT();
    };

    float o[8][4];
#pragma unroll
    for (int ni = 0; ni < 8; ni++)
#pragma unroll
        for (int j = 0; j < 4; j++) o[ni][j] = 0.f;
    float m0 = -1e30f, m1 = -1e30f, l0 = 0.f, l1 = 0.f;

    stage(0, 0);
    stage(1, 64);

    const int NT = SEQ / 64;
    for (int it = 0; it < NT; it++) {
        const int s = it & 1;
        if (it + 1 < NT) { CP_WAIT1(); } else { CP_WAIT0(); }
        __syncthreads();

        const uint32_t cKhiA = sKa  + (s * 2 + 0) * A_STG * 2;
        const uint32_t cKloA = sKa  + (s * 2 + 1) * A_STG * 2;
        const uint32_t cVhiA = sVTa + (s * 2 + 0) * A_STG * 2;
        const uint32_t cVloA = sVTa + (s * 2 + 1) * A_STG * 2;
        const uint32_t bOff  = ((uint32_t)brow * ASTR + bcol) * 2;

        // --- S = Q K^T (3 split terms) ---
        float sc[8][4];
#pragma unroll
        for (int ni = 0; ni < 8; ni++)
#pragma unroll
            for (int j = 0; j < 4; j++) sc[ni][j] = 0.f;

#pragma unroll
        for (int kj = 0; kj < 4; kj++) {
#pragma unroll
            for (int np = 0; np < 4; np++) {
                uint32_t off = bOff + ((uint32_t)np * 16 * ASTR + 16 * kj) * 2;
                uint32_t h0[2], h1[2], l0_[2], l1_[2];
                ldsm_x4(h0[0], h0[1], h1[0], h1[1], cKhiA + off);
                ldsm_x4(l0_[0], l0_[1], l1_[0], l1_[1], cKloA + off);
                mma16816(sc[2 * np],     qh[kj], h0);
                mma16816(sc[2 * np],     qh[kj], l0_);
                mma16816(sc[2 * np],     ql[kj], h0);
                mma16816(sc[2 * np + 1], qh[kj], h1);
                mma16816(sc[2 * np + 1], qh[kj], l1_);
                mma16816(sc[2 * np + 1], ql[kj], h1);
            }
        }

        // --- online softmax ---
        float mx0 = -1e30f, mx1 = -1e30f;
#pragma unroll
        for (int ni = 0; ni < 8; ni++) {
            sc[ni][0] *= 0.125f; sc[ni][1] *= 0.125f;
            sc[ni][2] *= 0.125f; sc[ni][3] *= 0.125f;
            mx0 = fmaxf(mx0, fmaxf(sc[ni][0], sc[ni][1]));
            mx1 = fmaxf(mx1, fmaxf(sc[ni][2], sc[ni][3]));
        }
        mx0 = fmaxf(mx0, __shfl_xor_sync(0xffffffff, mx0, 1));
        mx0 = fmaxf(mx0, __shfl_xor_sync(0xffffffff, mx0, 2));
        mx1 = fmaxf(mx1, __shfl_xor_sync(0xffffffff, mx1, 1));
        mx1 = fmaxf(mx1, __shfl_xor_sync(0xffffffff, mx1, 2));

        const float nm0 = fmaxf(m0, mx0);
        const float nm1 = fmaxf(m1, mx1);
        const float rs0 = __expf(m0 - nm0);
        const float rs1 = __expf(m1 - nm1);
        m0 = nm0; m1 = nm1;
        l0 *= rs0; l1 *= rs1;
#pragma unroll
        for (int ni = 0; ni < 8; ni++) {
            o[ni][0] *= rs0; o[ni][1] *= rs0;
            o[ni][2] *= rs1; o[ni][3] *= rs1;
            sc[ni][0] = __expf(sc[ni][0] - m0);
            sc[ni][1] = __expf(sc[ni][1] - m0);
            sc[ni][2] = __expf(sc[ni][2] - m1);
            sc[ni][3] = __expf(sc[ni][3] - m1);
            l0 += sc[ni][0] + sc[ni][1];
            l1 += sc[ni][2] + sc[ni][3];
        }

        // --- O += P V (3 split terms) ---
#pragma unroll
        for (int kj = 0; kj < 4; kj++) {
            uint32_t ah[4], al[4];
            hilo2(sc[2 * kj][0],     sc[2 * kj][1],     ah[0], al[0]);
            hilo2(sc[2 * kj][2],     sc[2 * kj][3],     ah[1], al[1]);
            hilo2(sc[2 * kj + 1][0], sc[2 * kj + 1][1], ah[2], al[2]);
            hilo2(sc[2 * kj + 1][2], sc[2 * kj + 1][3], ah[3], al[3]);
#pragma unroll
            for (int np = 0; np < 4; np++) {
                uint32_t off = bOff + ((uint32_t)np * 16 * ASTR + 16 * kj) * 2;
                uint32_t h0[2], h1[2], l0_[2], l1_[2];
                ldsm_x4(h0[0], h0[1], h1[0], h1[1], cVhiA + off);
                ldsm_x4(l0_[0], l0_[1], l1_[0], l1_[1], cVloA + off);
                mma16816(o[2 * np],     ah, h0);
                mma16816(o[2 * np],     ah, l0_);
                mma16816(o[2 * np],     al, h0);
                mma16816(o[2 * np + 1], ah, h1);
                mma16816(o[2 * np + 1], ah, l1_);
                mma16816(o[2 * np + 1], al, h1);
            }
        }

        __syncthreads();
        if (it + 2 < NT) stage(s, (it + 2) * 64);
    }

    // --- finalize ---
    l0 += __shfl_xor_sync(0xffffffff, l0, 1);
    l0 += __shfl_xor_sync(0xffffffff, l0, 2);
    l1 += __shfl_xor_sync(0xffffffff, l1, 1);
    l1 += __shfl_xor_sync(0xffffffff, l1, 2);
    const float inv0 = 1.f / l0;
    const float inv1 = 1.f / l1;

    const int s0 = qt * 64 + wid * 16 + g;
    const int b  = bh >> 4;
    const int h  = bh & 15;
    const size_t row0 = (size_t)(b * SEQ + s0) * K3;
    const size_t row1 = row0 + (size_t)8 * K3;

#pragma unroll
    for (int ni = 0; ni < 8; ni++) {
        const int col = h * 64 + 8 * ni + 2 * t;
        uint32_t hi0, lo0, hi1, lo1;
        hilo2(o[ni][0] * inv0, o[ni][1] * inv0, hi0, lo0);
        hilo2(o[ni][2] * inv1, o[ni][3] * inv1, hi1, lo1);
        *(uint32_t*)&Out[row0 + col]        = hi0;
        *(uint32_t*)&Out[row0 + col + 1024] = hi0;
        *(uint32_t*)&Out[row0 + col + 2048] = lo0;
        *(uint32_t*)&Out[row1 + col]        = hi1;
        *(uint32_t*)&Out[row1 + col + 1024] = hi1;
        *(uint32_t*)&Out[row1 + col + 2048] = lo1;
    }
}

// ---------------------------------------------------------------------------
extern "C" void kernel_launch(void* const* d_in, const int* in_sizes, int n_in,
                              void* d_out, int out_size)
{
    const float* X   = (const float*)d_in[0];
    const float* W_q = (const float*)d_in[1];
    const float* b_q = (const float*)d_in[2];
    const float* W_k = (const float*)d_in[3];
    const float* b_k = (const float*)d_in[4];
    const float* W_v = (const float*)d_in[5];
    const float* b_v = (const float*)d_in[6];
    const float* W_o = (const float*)d_in[7];
    const float* b_o = (const float*)d_in[8];
    float* out = (float*)d_out;

    __nv_bfloat16 *Qhi, *Qlo, *Khi, *Klo, *VThi, *VTlo, *Xs, *Ws, *As;
    cudaGetSymbolAddress((void**)&Qhi, g_Qhi);
    cudaGetSymbolAddress((void**)&Qlo, g_Qlo);
    cudaGetSymbolAddress((void**)&Khi, g_Khi);
    cudaGetSymbolAddress((void**)&Klo, g_Klo);
    cudaGetSymbolAddress((void**)&VThi, g_VThi);
    cudaGetSymbolAddress((void**)&VTlo, g_VTlo);
    cudaGetSymbolAddress((void**)&Xs, g_Xs);
    cudaGetSymbolAddress((void**)&Ws, g_Ws);
    cudaGetSymbolAddress((void**)&As, g_As);

    cudaFuncSetAttribute(gemm_mma_kernel, cudaFuncAttributeMaxDynamicSharedMemorySize, G_SMEM);
    cudaFuncSetAttribute(attn_mma_kernel, cudaFuncAttributeMaxDynamicSharedMemorySize, ATT_SMEM);

    const int cthr = 256;
    split_x_kernel<<<MROWS * EMB / (cthr * 4), cthr>>>(X, Xs);
    dim3 wgrid(EMB * EMB / (cthr * 4), 4);
    split_w_kernel<<<wgrid, cthr>>>(W_q, W_k, W_v, W_o, Ws);

    // fused QKV (V written pre-transposed): N = 3072, tile 128x128
    dim3 qkvgrid(K3 / 128, MROWS / 128);   // (24, 32)
    gemm_mma_kernel<<<qkvgrid, 256, G_SMEM>>>(Xs, Ws, b_q, b_k, b_v,
                                              Qhi, Qlo, Khi, Klo, VThi, VTlo, nullptr, 0);

    dim3 agrid(SEQ / 64, BATCH * NHEAD);
    attn_mma_kernel<<<agrid, 128, ATT_SMEM>>>(Qhi, Qlo, Khi, Klo, VThi, VTlo, As);

    // O-projection: N = 1024
    dim3 ogrid(EMB / 128, MROWS / 128);    // (8, 32)
    gemm_mma_kernel<<<ogrid, 256, G_SMEM>>>(As, Ws + 3 * (size_t)EMB * K3, b_o, nullptr, nullptr,
                                            nullptr, nullptr, nullptr, nullptr, nullptr, nullptr,
                                            out, 1);
}

// round 13
// speedup vs baseline: 1.0952x; 1.0143x over previous
#include <cuda_runtime.h>
#include <cuda_bf16.h>
#include <stdint.h>
#include <math.h>

#define BATCH   2
#define SEQ     2048
#define EMB     1024
#define NHEAD   16
#define HDIM    64
#define MROWS   (BATCH * SEQ)
#define K3      (3 * EMB)
#define QKV_ELEMS (BATCH * NHEAD * SEQ * HDIM)

// Scratch (__device__ globals)
__device__ __nv_bfloat16 g_Qhi[QKV_ELEMS];
__device__ __nv_bfloat16 g_Qlo[QKV_ELEMS];
__device__ __nv_bfloat16 g_Khi[QKV_ELEMS];
__device__ __nv_bfloat16 g_Klo[QKV_ELEMS];
__device__ __nv_bfloat16 g_VThi[QKV_ELEMS];   // [B,H,D,S]
__device__ __nv_bfloat16 g_VTlo[QKV_ELEMS];
__device__ __nv_bfloat16 g_Xs[(size_t)MROWS * K3];
__device__ __nv_bfloat16 g_Ws[4][(size_t)EMB * K3];
__device__ __nv_bfloat16 g_As[(size_t)MROWS * K3];

// ---------------------------------------------------------------------------
__device__ __forceinline__ uint32_t smem_u32(const void* p) {
    uint32_t a;
    asm("{ .reg .u64 t; cvta.to.shared.u64 t, %1; cvt.u32.u64 %0, t; }" : "=r"(a) : "l"(p));
    return a;
}
#define CP_ASYNC16(dst, src) asm volatile("cp.async.cg.shared.global [%0], [%1], 16;" :: "r"(dst), "l"(src))
#define CP_COMMIT()  asm volatile("cp.async.commit_group;" ::: "memory")
#define CP_WAIT2()   asm volatile("cp.async.wait_group 2;" ::: "memory")
#define CP_WAIT1()   asm volatile("cp.async.wait_group 1;" ::: "memory")
#define CP_WAIT0()   asm volatile("cp.async.wait_group 0;" ::: "memory")

__device__ __forceinline__ void ldsm_x4(uint32_t& r0, uint32_t& r1, uint32_t& r2, uint32_t& r3,
                                        uint32_t addr)
{
    asm volatile("ldmatrix.sync.aligned.m8n8.x4.shared.b16 {%0,%1,%2,%3}, [%4];"
        : "=r"(r0), "=r"(r1), "=r"(r2), "=r"(r3) : "r"(addr));
}

__device__ __forceinline__ void hilo2(float x, float y, uint32_t& hi, uint32_t& lo)
{
    __nv_bfloat16 hx = __float2bfloat16(x), hy = __float2bfloat16(y);
    __nv_bfloat16 lx = __float2bfloat16(x - __bfloat162float(hx));
    __nv_bfloat16 ly = __float2bfloat16(y - __bfloat162float(hy));
    __nv_bfloat162 h2; h2.x = hx; h2.y = hy;
    __nv_bfloat162 l2; l2.x = lx; l2.y = ly;
    hi = *(uint32_t*)&h2;
    lo = *(uint32_t*)&l2;
}

__device__ __forceinline__ void hilo1(float x, __nv_bfloat16& h, __nv_bfloat16& l)
{
    h = __float2bfloat16(x);
    l = __float2bfloat16(x - __bfloat162float(h));
}

__device__ __forceinline__ void mma16816(float* c, const uint32_t* a, const uint32_t* b)
{
    asm volatile(
        "mma.sync.aligned.m16n8k16.row.col.f32.bf16.bf16.f32 "
        "{%0,%1,%2,%3}, {%4,%5,%6,%7}, {%8,%9}, {%0,%1,%2,%3};"
        : "+f"(c[0]), "+f"(c[1]), "+f"(c[2]), "+f"(c[3])
        : "r"(a[0]), "r"(a[1]), "r"(a[2]), "r"(a[3]), "r"(b[0]), "r"(b[1]));
}

// ---------------------------------------------------------------------------
// Split conversion kernels (vectorized: 4 elems/thread, 8B stores)
// ---------------------------------------------------------------------------
__device__ __forceinline__ uint2 pack4hi(float a, float b, float c, float d)
{
    __nv_bfloat162 p0; p0.x = __float2bfloat16(a); p0.y = __float2bfloat16(b);
    __nv_bfloat162 p1; p1.x = __float2bfloat16(c); p1.y = __float2bfloat16(d);
    uint2 r; r.x = *(uint32_t*)&p0; r.y = *(uint32_t*)&p1;
    return r;
}
__device__ __forceinline__ uint2 pack4lo(float a, float b, float c, float d)
{
    __nv_bfloat16 ha = __float2bfloat16(a), hb = __float2bfloat16(b);
    __nv_bfloat16 hc = __float2bfloat16(c), hd = __float2bfloat16(d);
    __nv_bfloat162 p0; p0.x = __float2bfloat16(a - __bfloat162float(ha));
    p0.y = __float2bfloat16(b - __bfloat162float(hb));
    __nv_bfloat162 p1; p1.x = __float2bfloat16(c - __bfloat162float(hc));
    p1.y = __float2bfloat16(d - __bfloat162float(hd));
    uint2 r; r.x = *(uint32_t*)&p0; r.y = *(uint32_t*)&p1;
    return r;
}

__global__ void split_x_kernel(const float* __restrict__ in,
                               __nv_bfloat16* __restrict__ out)
{
    int idx = (blockIdx.x * blockDim.x + threadIdx.x) * 4;
    int r = idx >> 10;
    int k = idx & 1023;
    float4 x = *(const float4*)(in + idx);
    uint2 hh = pack4hi(x.x, x.y, x.z, x.w);
    uint2 ll = pack4lo(x.x, x.y, x.z, x.w);
    __nv_bfloat16* o = out + (size_t)r * K3 + k;
    *(uint2*)(o)        = hh;
    *(uint2*)(o + 1024) = hh;
    *(uint2*)(o + 2048) = ll;
}

__global__ void split_w_kernel(const float* __restrict__ W0, const float* __restrict__ W1,
                               const float* __restrict__ W2, const float* __restrict__ W3,
                               __nv_bfloat16* __restrict__ out)
{
    int w = blockIdx.y;
    const float* in = (w == 0) ? W0 : (w == 1) ? W1 : (w == 2) ? W2 : W3;
    int idx = (blockIdx.x * blockDim.x + threadIdx.x) * 4;
    int r = idx >> 10;
    int k = idx & 1023;
    float4 x = *(const float4*)(in + idx);
    uint2 hh = pack4hi(x.x, x.y, x.z, x.w);
    uint2 ll = pack4lo(x.x, x.y, x.z, x.w);
    __nv_bfloat16* o = out + (size_t)w * EMB * K3 + (size_t)r * K3 + k;
    *(uint2*)(o)        = hh;
    *(uint2*)(o + 1024) = ll;
    *(uint2*)(o + 2048) = hh;
}

// ---------------------------------------------------------------------------
// bf16 HMMA GEMM: CTA 128x128, 8 warps (64x32), K=3072, KCH=32, GPAD=40,
// FOUR stages processed in chunk-pairs (one wait + 2 barriers per 64 K),
// ldmatrix, occ 2. Inner k16 body identical to R12.
// mode 0: fused QKV (Q scaled by 0.125); Q/K split [B,H,S,D], V TRANSPOSED.
// mode 1: O-projection, fp32 row-major.
// ---------------------------------------------------------------------------
#define GPAD   40
#define KCH    32
#define NPAIR  (K3 / (2 * KCH))            // 48
#define STG_B  (128 * GPAD * 2)            // 10240 B per array per stage
#define G_SMEM (2 * 4 * STG_B)             // 81920 B

__global__ void __launch_bounds__(256, 2)
gemm_mma_kernel(const __nv_bfloat16* __restrict__ A,
                const __nv_bfloat16* __restrict__ B,
                const float* __restrict__ bias0, const float* __restrict__ bias1,
                const float* __restrict__ bias2,
                __nv_bfloat16* __restrict__ Qhi, __nv_bfloat16* __restrict__ Qlo,
                __nv_bfloat16* __restrict__ Khi, __nv_bfloat16* __restrict__ Klo,
                __nv_bfloat16* __restrict__ VThi, __nv_bfloat16* __restrict__ VTlo,
                float* __restrict__ Cf, int mode)
{
    extern __shared__ __nv_bfloat16 smraw[];

    const int tid  = threadIdx.x;
    const int wid  = tid >> 5;
    const int lane = tid & 31;
    const int g    = lane >> 2;
    const int t    = lane & 3;
    const int bm   = blockIdx.y;
    const int bn   = blockIdx.x;
    const int wm   = (wid >> 2) * 64;
    const int wn   = (wid & 3) * 32;

    const int arow = (lane & 7) + ((lane >> 3) & 1) * 8;
    const int acol = (lane >> 4) * 8;
    const int brow = (lane & 7) + ((lane >> 4) & 1) * 8;
    const int bcol = ((lane >> 3) & 1) * 8;

    const uint32_t aBase = smem_u32(smraw);          // As[4][128][GPAD]
    const uint32_t bBase = aBase + 4 * STG_B;        // Bs[4][128][GPAD]

    const int lrow = tid >> 1;
    const int lco  = (tid & 1) * 16;
    const __nv_bfloat16* Ag = A + (size_t)(bm * 128 + lrow) * K3 + lco;
    const __nv_bfloat16* Bg = B + (size_t)(bn * 128 + lrow) * K3 + lco;
    const uint32_t dA = aBase + ((uint32_t)lrow * GPAD + lco) * 2;
    const uint32_t dB = bBase + ((uint32_t)lrow * GPAD + lco) * 2;

    // load a PAIR of chunks (k0, k0+KCH) into stages sp, sp+1; ONE commit
    auto load_pair = [&](int sp, int k0) {
        CP_ASYNC16(dA + sp * STG_B,            Ag + k0);
        CP_ASYNC16(dA + sp * STG_B + 16,       Ag + k0 + 8);
        CP_ASYNC16(dB + sp * STG_B,            Bg + k0);
        CP_ASYNC16(dB + sp * STG_B + 16,       Bg + k0 + 8);
        CP_ASYNC16(dA + (sp + 1) * STG_B,      Ag + k0 + KCH);
        CP_ASYNC16(dA + (sp + 1) * STG_B + 16, Ag + k0 + KCH + 8);
        CP_ASYNC16(dB + (sp + 1) * STG_B,      Bg + k0 + KCH);
        CP_ASYNC16(dB + (sp + 1) * STG_B + 16, Bg + k0 + KCH + 8);
        CP_COMMIT();
    };

    float acc[4][4][4];
#pragma unroll
    for (int i = 0; i < 4; i++)
#pragma unroll
        for (int j = 0; j < 4; j++)
#pragma unroll
            for (int q = 0; q < 4; q++) acc[i][j][q] = 0.f;

    load_pair(0, 0);          // pair 0 -> stages 0,1
    load_pair(2, 2 * KCH);    // pair 1 -> stages 2,3

    for (int p = 0; p < NPAIR; p++) {
        const int sp = (p & 1) * 2;
        if (p + 1 < NPAIR) { CP_WAIT1(); } else { CP_WAIT0(); }
        __syncthreads();

#pragma unroll
        for (int half = 0; half < 2; half++) {
            const uint32_t aS = aBase + (sp + half) * STG_B;
            const uint32_t bS = bBase + (sp + half) * STG_B;
#pragma unroll
            for (int kk = 0; kk < KCH; kk += 16) {
                uint32_t af[4][4], bf[4][2];
#pragma unroll
                for (int mi = 0; mi < 4; mi++) {
                    uint32_t addr = aS + (((uint32_t)(wm + mi * 16 + arow)) * GPAD + kk + acol) * 2;
                    ldsm_x4(af[mi][0], af[mi][1], af[mi][2], af[mi][3], addr);
                }
#pragma unroll
                for (int np = 0; np < 2; np++) {
                    uint32_t addr = bS + (((uint32_t)(wn + np * 16 + brow)) * GPAD + kk + bcol) * 2;
                    ldsm_x4(bf[2 * np][0], bf[2 * np][1], bf[2 * np + 1][0], bf[2 * np + 1][1], addr);
                }
#pragma unroll
                for (int mi = 0; mi < 4; mi++)
#pragma unroll
                    for (int ni = 0; ni < 4; ni++)
                        mma16816(acc[mi][ni], af[mi], bf[ni]);
            }
        }
        __syncthreads();
        if (p + 2 < NPAIR) load_pair(sp, (p + 2) * 2 * KCH);
    }

    // epilogue
#pragma unroll
    for (int mi = 0; mi < 4; mi++) {
        const int r0 = bm * 128 + wm + mi * 16 + g;
#pragma unroll
        for (int ni = 0; ni < 4; ni++) {
            const int c = bn * 128 + wn + ni * 8 + 2 * t;
            if (mode == 0) {
                const int which = c >> 10;
                const int cc    = c & 1023;
                const float* bp = (which == 0) ? bias0 : (which == 1) ? bias1 : bias2;
                const float bv0 = bp[cc], bv1 = bp[cc + 1];
                float v00 = acc[mi][ni][0] + bv0, v01 = acc[mi][ni][1] + bv1;
                float v10 = acc[mi][ni][2] + bv0, v11 = acc[mi][ni][3] + bv1;
                const int b = r0 >> 11, sq = r0 & 2047;
                const int h = cc >> 6, d = cc & 63;
                if (which == 0) {
                    // fold softmax scale 1/sqrt(64) into Q (exact power of 2)
                    v00 *= 0.125f; v01 *= 0.125f; v10 *= 0.125f; v11 *= 0.125f;
                }
                if (which < 2) {
                    size_t off0 = (((size_t)(b * NHEAD + h) * SEQ) + sq) * HDIM + d;
                    size_t off1 = off0 + 8 * HDIM;
                    __nv_bfloat16* Hh = (which == 0) ? Qhi : Khi;
                    __nv_bfloat16* Ll = (which == 0) ? Qlo : Klo;
                    uint32_t hi0, lo0, hi1, lo1;
                    hilo2(v00, v01, hi0, lo0);
                    hilo2(v10, v11, hi1, lo1);
                    *(uint32_t*)(Hh + off0) = hi0;
                    *(uint32_t*)(Ll + off0) = lo0;
                    *(uint32_t*)(Hh + off1) = hi1;
                    *(uint32_t*)(Ll + off1) = lo1;
                } else {
                    size_t offT = (((size_t)(b * NHEAD + h) * HDIM) + d) * SEQ + sq;
                    __nv_bfloat16 h00, l00, h01, l01, h10, l10, h11, l11;
                    hilo1(v00, h00, l00);
                    hilo1(v01, h01, l01);
                    hilo1(v10, h10, l10);
                    hilo1(v11, h11, l11);
                    VThi[offT]           = h00;
                    VThi[offT + 8]       = h10;
                    VThi[offT + SEQ]     = h01;
                    VThi[offT + SEQ + 8] = h11;
                    VTlo[offT]           = l00;
                    VTlo[offT + 8]       = l10;
                    VTlo[offT + SEQ]     = l01;
                    VTlo[offT + SEQ + 8] = l11;
                }
            } else {
                const float bv0 = bias0[c], bv1 = bias0[c + 1];
                *(float2*)(Cf + (size_t)r0 * EMB + c) =
                    make_float2(acc[mi][ni][0] + bv0, acc[mi][ni][1] + bv1);
                *(float2*)(Cf + (size_t)(r0 + 8) * EMB + c) =
                    make_float2(acc[mi][ni][2] + bv0, acc[mi][ni][3] + bv1);
            }
        }
    }
}

// ---------------------------------------------------------------------------
// Tensor-core flash attention (R9 structure; Q pre-scaled so no 0.125 mults).
// Br=64, cp.async double-buffer, ldmatrix frags, occ 3.
// ---------------------------------------------------------------------------
#define ASTR 72
#define A_STG (64 * ASTR)
#define ATT_SMEM (8 * A_STG * 2)

__global__ void __launch_bounds__(128, 3)
attn_mma_kernel(const __nv_bfloat16* __restrict__ Qhi, const __nv_bfloat16* __restrict__ Qlo,
                const __nv_bfloat16* __restrict__ Khi, const __nv_bfloat16* __restrict__ Klo,
                const __nv_bfloat16* __restrict__ VThi, const __nv_bfloat16* __restrict__ VTlo,
                __nv_bfloat16* __restrict__ Out)
{
    extern __shared__ __nv_bfloat16 sm[];
    __nv_bfloat16* sK  = sm;
    __nv_bfloat16* sVT = sm + 4 * A_STG;

    const int tid  = threadIdx.x;
    const int wid  = tid >> 5;
    const int lane = tid & 31;
    const int g    = lane >> 2;
    const int t    = lane & 3;
    const int qt   = blockIdx.x;
    const int bh   = blockIdx.y;
    const size_t base  = (size_t)bh * SEQ * HDIM;
    const size_t baseT = (size_t)bh * HDIM * SEQ;

    const int brow = (lane & 7) + ((lane >> 4) & 1) * 8;
    const int bcol = ((lane >> 3) & 1) * 8;

    // --- Stage Q tile into sK stage 0, extract frags ---
#pragma unroll
    for (int i = 0; i < 4; i++) {
        int idx = tid + 128 * i;
        int row = idx >> 3;
        int co  = (idx & 7) * 8;
        *(uint4*)&sK[row * ASTR + co]         = *(const uint4*)&Qhi[base + (size_t)(qt * 64 + row) * HDIM + co];
        *(uint4*)&sK[A_STG + row * ASTR + co] = *(const uint4*)&Qlo[base + (size_t)(qt * 64 + row) * HDIM + co];
    }
    __syncthreads();

    uint32_t qh[4][4], ql[4][4];
    {
        const int arow = (lane & 7) + ((lane >> 3) & 1) * 8;
        const int acol = (lane >> 4) * 8;
        const uint32_t qBase = smem_u32(sK);
#pragma unroll
        for (int kj = 0; kj < 4; kj++) {
            uint32_t ah = qBase + (((uint32_t)(wid * 16 + arow)) * ASTR + 16 * kj + acol) * 2;
            ldsm_x4(qh[kj][0], qh[kj][1], qh[kj][2], qh[kj][3], ah);
            ldsm_x4(ql[kj][0], ql[kj][1], ql[kj][2], ql[kj][3], ah + A_STG * 2);
        }
    }
    __syncthreads();

    const uint32_t sKa  = smem_u32(sK);
    const uint32_t sVTa = smem_u32(sVT);
    auto stage = [&](int st, int kt) {
#pragma unroll
        for (int j = 0; j < 4; j++) {
            int id  = tid + 128 * j;
            int row = id >> 3;
            int co  = (id & 7) * 8;
            uint32_t so = ((uint32_t)row * ASTR + co) * 2;
            CP_ASYNC16(sKa  + (st * 2 + 0) * A_STG * 2 + so, Khi  + base  + (size_t)(kt + row) * HDIM + co);
            CP_ASYNC16(sKa  + (st * 2 + 1) * A_STG * 2 + so, Klo  + base  + (size_t)(kt + row) * HDIM + co);
            CP_ASYNC16(sVTa + (st * 2 + 0) * A_STG * 2 + so, VThi + baseT + (size_t)row * SEQ + kt + co);
            CP_ASYNC16(sVTa + (st * 2 + 1) * A_STG * 2 + so, VTlo + baseT + (size_t)row * SEQ + kt + co);
        }
        CP_COMMIT();
    };

    float o[8][4];
#pragma unroll
    for (int ni = 0; ni < 8; ni++)
#pragma unroll
        for (int j = 0; j < 4; j++) o[ni][j] = 0.f;
    float m0 = -1e30f, m1 = -1e30f, l0 = 0.f, l1 = 0.f;

    stage(0, 0);
    stage(1, 64);

    const int NT = SEQ / 64;
    for (int it = 0; it < NT; it++) {
        const int s = it & 1;
        if (it + 1 < NT) { CP_WAIT1(); } else { CP_WAIT0(); }
        __syncthreads();

        const uint32_t cKhiA = sKa  + (s * 2 + 0) * A_STG * 2;
        const uint32_t cKloA = sKa  + (s * 2 + 1) * A_STG * 2;
        const uint32_t cVhiA = sVTa + (s * 2 + 0) * A_STG * 2;
        const uint32_t cVloA = sVTa + (s * 2 + 1) * A_STG * 2;
        const uint32_t bOff  = ((uint32_t)brow * ASTR + bcol) * 2;

        // --- S = Q K^T (3 split terms; scale pre-folded into Q) ---
        float sc[8][4];
#pragma unroll
        for (int ni = 0; ni < 8; ni++)
#pragma unroll
            for (int j = 0; j < 4; j++) sc[ni][j] = 0.f;

#pragma unroll
        for (int kj = 0; kj < 4; kj++) {
#pragma unroll
            for (int np = 0; np < 4; np++) {
                uint32_t off = bOff + ((uint32_t)np * 16 * ASTR + 16 * kj) * 2;
                uint32_t h0[2], h1[2], l0_[2], l1_[2];
                ldsm_x4(h0[0], h0[1], h1[0], h1[1], cKhiA + off);
                ldsm_x4(l0_[0], l0_[1], l1_[0], l1_[1], cKloA + off);
                mma16816(sc[2 * np],     qh[kj], h0);
                mma16816(sc[2 * np],     qh[kj], l0_);
                mma16816(sc[2 * np],     ql[kj], h0);
                mma16816(sc[2 * np + 1], qh[kj], h1);
                mma16816(sc[2 * np + 1], qh[kj], l1_);
                mma16816(sc[2 * np + 1], ql[kj], h1);
            }
        }

        // --- online softmax (no scale mults needed) ---
        float mx0 = -1e30f, mx1 = -1e30f;
#pragma unroll
        for (int ni = 0; ni < 8; ni++) {
            mx0 = fmaxf(mx0, fmaxf(sc[ni][0], sc[ni][1]));
            mx1 = fmaxf(mx1, fmaxf(sc[ni][2], sc[ni][3]));
        }
        mx0 = fmaxf(mx0, __shfl_xor_sync(0xffffffff, mx0, 1));
        mx0 = fmaxf(mx0, __shfl_xor_sync(0xffffffff, mx0, 2));
        mx1 = fmaxf(mx1, __shfl_xor_sync(0xffffffff, mx1, 1));
        mx1 = fmaxf(mx1, __shfl_xor_sync(0xffffffff, mx1, 2));

        const float nm0 = fmaxf(m0, mx0);
        const float nm1 = fmaxf(m1, mx1);
        const float rs0 = __expf(m0 - nm0);
        const float rs1 = __expf(m1 - nm1);
        m0 = nm0; m1 = nm1;
        l0 *= rs0; l1 *= rs1;
#pragma unroll
        for (int ni = 0; ni < 8; ni++) {
            o[ni][0] *= rs0; o[ni][1] *= rs0;
            o[ni][2] *= rs1; o[ni][3] *= rs1;
            sc[ni][0] = __expf(sc[ni][0] - m0);
            sc[ni][1] = __expf(sc[ni][1] - m0);
            sc[ni][2] = __expf(sc[ni][2] - m1);
            sc[ni][3] = __expf(sc[ni][3] - m1);
            l0 += sc[ni][0] + sc[ni][1];
            l1 += sc[ni][2] + sc[ni][3];
        }

        // --- O += P V (3 split terms) ---
#pragma unroll
        for (int kj = 0; kj < 4; kj++) {
            uint32_t ah[4], al[4];
            hilo2(sc[2 * kj][0],     sc[2 * kj][1],     ah[0], al[0]);
            hilo2(sc[2 * kj][2],     sc[2 * kj][3],     ah[1], al[1]);
            hilo2(sc[2 * kj + 1][0], sc[2 * kj + 1][1], ah[2], al[2]);
            hilo2(sc[2 * kj + 1][2], sc[2 * kj + 1][3], ah[3], al[3]);
#pragma unroll
            for (int np = 0; np < 4; np++) {
                uint32_t off = bOff + ((uint32_t)np * 16 * ASTR + 16 * kj) * 2;
                uint32_t h0[2], h1[2], l0_[2], l1_[2];
                ldsm_x4(h0[0], h0[1], h1[0], h1[1], cVhiA + off);
                ldsm_x4(l0_[0], l0_[1], l1_[0], l1_[1], cVloA + off);
                mma16816(o[2 * np],     ah, h0);
                mma16816(o[2 * np],     ah, l0_);
                mma16816(o[2 * np],     al, h0);
                mma16816(o[2 * np + 1], ah, h1);
                mma16816(o[2 * np + 1], ah, l1_);
                mma16816(o[2 * np + 1], al, h1);
            }
        }

        __syncthreads();
        if (it + 2 < NT) stage(s, (it + 2) * 64);
    }

    // --- finalize ---
    l0 += __shfl_xor_sync(0xffffffff, l0, 1);
    l0 += __shfl_xor_sync(0xffffffff, l0, 2);
    l1 += __shfl_xor_sync(0xffffffff, l1, 1);
    l1 += __shfl_xor_sync(0xffffffff, l1, 2);
    const float inv0 = 1.f / l0;
    const float inv1 = 1.f / l1;

    const int s0 = qt * 64 + wid * 16 + g;
    const int b  = bh >> 4;
    const int h  = bh & 15;
    const size_t row0 = (size_t)(b * SEQ + s0) * K3;
    const size_t row1 = row0 + (size_t)8 * K3;

#pragma unroll
    for (int ni = 0; ni < 8; ni++) {
        const int col = h * 64 + 8 * ni + 2 * t;
        uint32_t hi0, lo0, hi1, lo1;
        hilo2(o[ni][0] * inv0, o[ni][1] * inv0, hi0, lo0);
        hilo2(o[ni][2] * inv1, o[ni][3] * inv1, hi1, lo1);
        *(uint32_t*)&Out[row0 + col]        = hi0;
        *(uint32_t*)&Out[row0 + col + 1024] = hi0;
        *(uint32_t*)&Out[row0 + col + 2048] = lo0;
        *(uint32_t*)&Out[row1 + col]        = hi1;
        *(uint32_t*)&Out[row1 + col + 1024] = hi1;
        *(uint32_t*)&Out[row1 + col + 2048] = lo1;
    }
}

// ---------------------------------------------------------------------------
extern "C" void kernel_launch(void* const* d_in, const int* in_sizes, int n_in,
                              void* d_out, int out_size)
{
    const float* X   = (const float*)d_in[0];
    const float* W_q = (const float*)d_in[1];
    const float* b_q = (const float*)d_in[2];
    const float* W_k = (const float*)d_in[3];
    const float* b_k = (const float*)d_in[4];
    const float* W_v = (const float*)d_in[5];
    const float* b_v = (const float*)d_in[6];
    const float* W_o = (const float*)d_in[7];
    const float* b_o = (const float*)d_in[8];
    float* out = (float*)d_out;

    __nv_bfloat16 *Qhi, *Qlo, *Khi, *Klo, *VThi, *VTlo, *Xs, *Ws, *As;
    cudaGetSymbolAddress((void**)&Qhi, g_Qhi);
    cudaGetSymbolAddress((void**)&Qlo, g_Qlo);
    cudaGetSymbolAddress((void**)&Khi, g_Khi);
    cudaGetSymbolAddress((void**)&Klo, g_Klo);
    cudaGetSymbolAddress((void**)&VThi, g_VThi);
    cudaGetSymbolAddress((void**)&VTlo, g_VTlo);
    cudaGetSymbolAddress((void**)&Xs, g_Xs);
    cudaGetSymbolAddress((void**)&Ws, g_Ws);
    cudaGetSymbolAddress((void**)&As, g_As);

    cudaFuncSetAttribute(gemm_mma_kernel, cudaFuncAttributeMaxDynamicSharedMemorySize, G_SMEM);
    cudaFuncSetAttribute(attn_mma_kernel, cudaFuncAttributeMaxDynamicSharedMemorySize, ATT_SMEM);

    const int cthr = 256;
    split_x_kernel<<<MROWS * EMB / (cthr * 4), cthr>>>(X, Xs);
    dim3 wgrid(EMB * EMB / (cthr * 4), 4);
    split_w_kernel<<<wgrid, cthr>>>(W_q, W_k, W_v, W_o, Ws);

    // fused QKV (V written pre-transposed, Q pre-scaled): N = 3072
    dim3 qkvgrid(K3 / 128, MROWS / 128);   // (24, 32)
    gemm_mma_kernel<<<qkvgrid, 256, G_SMEM>>>(Xs, Ws, b_q, b_k, b_v,
                                              Qhi, Qlo, Khi, Klo, VThi, VTlo, nullptr, 0);

    dim3 agrid(SEQ / 64, BATCH * NHEAD);
    attn_mma_kernel<<<agrid, 128, ATT_SMEM>>>(Qhi, Qlo, Khi, Klo, VThi, VTlo, As);

    // O-projection: N = 1024
    dim3 ogrid(EMB / 128, MROWS / 128);    // (8, 32)
    gemm_mma_kernel<<<ogrid, 256, G_SMEM>>>(As, Ws + 3 * (size_t)EMB * K3, b_o, nullptr, nullptr,
                                            nullptr, nullptr, nullptr, nullptr, nullptr, nullptr,
                                            out, 1);
}

// round 14
// speedup vs baseline: 1.5507x; 1.4158x over previous
#include <cuda_runtime.h>
#include <cuda_fp16.h>
#include <stdint.h>
#include <math.h>

#define BATCH   2
#define SEQ     2048
#define EMB     1024
#define NHEAD   16
#define HDIM    64
#define MROWS   (BATCH * SEQ)
#define K2      (2 * EMB)              // 2048: fp16 2-term concat
#define QKV_ELEMS (BATCH * NHEAD * SEQ * HDIM)

// Scratch (__device__ globals)
__device__ __half g_Qh[QKV_ELEMS];            // Q hi only (pre-scaled 0.125)
__device__ __half g_Khi[QKV_ELEMS];
__device__ __half g_Klo[QKV_ELEMS];
__device__ __half g_VThi[QKV_ELEMS];          // [B,H,D,S]
__device__ __half g_VTlo[QKV_ELEMS];
__device__ __half g_Xs[(size_t)MROWS * K2];   // [xh | xh]
__device__ __half g_Ws[4][(size_t)EMB * K2];  // [wh | wl]
__device__ __half g_As[(size_t)MROWS * K2];   // [ah | ah]

// ---------------------------------------------------------------------------
__device__ __forceinline__ uint32_t smem_u32(const void* p) {
    uint32_t a;
    asm("{ .reg .u64 t; cvta.to.shared.u64 t, %1; cvt.u32.u64 %0, t; }" : "=r"(a) : "l"(p));
    return a;
}
#define CP_ASYNC16(dst, src) asm volatile("cp.async.cg.shared.global [%0], [%1], 16;" :: "r"(dst), "l"(src))
#define CP_COMMIT()  asm volatile("cp.async.commit_group;" ::: "memory")
#define CP_WAIT1()   asm volatile("cp.async.wait_group 1;" ::: "memory")
#define CP_WAIT0()   asm volatile("cp.async.wait_group 0;" ::: "memory")

__device__ __forceinline__ void ldsm_x4(uint32_t& r0, uint32_t& r1, uint32_t& r2, uint32_t& r3,
                                        uint32_t addr)
{
    asm volatile("ldmatrix.sync.aligned.m8n8.x4.shared.b16 {%0,%1,%2,%3}, [%4];"
        : "=r"(r0), "=r"(r1), "=r"(r2), "=r"(r3) : "r"(addr));
}

__device__ __forceinline__ uint32_t packh2(float x, float y)
{
    __half2 h = __floats2half2_rn(x, y);
    return *(uint32_t*)&h;
}

__device__ __forceinline__ void hilo2h(float x, float y, uint32_t& hi, uint32_t& lo)
{
    __half hx = __float2half_rn(x), hy = __float2half_rn(y);
    __half lx = __float2half_rn(x - __half2float(hx));
    __half ly = __float2half_rn(y - __half2float(hy));
    __half2 h2 = __halves2half2(hx, hy);
    __half2 l2 = __halves2half2(lx, ly);
    hi = *(uint32_t*)&h2;
    lo = *(uint32_t*)&l2;
}

__device__ __forceinline__ void hilo1h(float x, __half& h, __half& l)
{
    h = __float2half_rn(x);
    l = __float2half_rn(x - __half2float(h));
}

__device__ __forceinline__ void mma16816(float* c, const uint32_t* a, const uint32_t* b)
{
    asm volatile(
        "mma.sync.aligned.m16n8k16.row.col.f32.f16.f16.f32 "
        "{%0,%1,%2,%3}, {%4,%5,%6,%7}, {%8,%9}, {%0,%1,%2,%3};"
        : "+f"(c[0]), "+f"(c[1]), "+f"(c[2]), "+f"(c[3])
        : "r"(a[0]), "r"(a[1]), "r"(a[2]), "r"(a[3]), "r"(b[0]), "r"(b[1]));
}

// ---------------------------------------------------------------------------
// Split conversion kernels (fp16; activations hi-replicated, weights hi/lo)
// ---------------------------------------------------------------------------
__global__ void split_x_kernel(const float* __restrict__ in,
                               __half* __restrict__ out)
{
    int idx = (blockIdx.x * blockDim.x + threadIdx.x) * 4;
    int r = idx >> 10;
    int k = idx & 1023;
    float4 x = *(const float4*)(in + idx);
    uint2 hh;
    hh.x = packh2(x.x, x.y);
    hh.y = packh2(x.z, x.w);
    __half* o = out + (size_t)r * K2 + k;
    *(uint2*)(o)        = hh;
    *(uint2*)(o + 1024) = hh;
}

__global__ void split_w_kernel(const float* __restrict__ W0, const float* __restrict__ W1,
                               const float* __restrict__ W2, const float* __restrict__ W3,
                               __half* __restrict__ out)
{
    int w = blockIdx.y;
    const float* in = (w == 0) ? W0 : (w == 1) ? W1 : (w == 2) ? W2 : W3;
    int idx = (blockIdx.x * blockDim.x + threadIdx.x) * 4;
    int r = idx >> 10;
    int k = idx & 1023;
    float4 x = *(const float4*)(in + idx);
    uint32_t h0, l0, h1, l1;
    hilo2h(x.x, x.y, h0, l0);
    hilo2h(x.z, x.w, h1, l1);
    uint2 hh; hh.x = h0; hh.y = h1;
    uint2 ll; ll.x = l0; ll.y = l1;
    __half* o = out + (size_t)w * EMB * K2 + (size_t)r * K2 + k;
    *(uint2*)(o)        = hh;
    *(uint2*)(o + 1024) = ll;
}

// ---------------------------------------------------------------------------
// fp16 HMMA GEMM: CTA 128x128, 8 warps (64x32), K=2048, KCH=32, GPAD=40,
// 4 stages in chunk-pairs, ldmatrix, occ 2.  (R13 structure, fp16 types.)
// mode 0: fused QKV; Q hi-only (scaled 0.125) [B,H,S,D], K hi/lo [B,H,S,D],
//         V hi/lo TRANSPOSED [B,H,D,S].
// mode 1: O-projection, fp32 row-major.
// ---------------------------------------------------------------------------
#define GPAD   40
#define KCH    32
#define NPAIR  (K2 / (2 * KCH))            // 32
#define STG_B  (128 * GPAD * 2)            // 10240 B
#define G_SMEM (2 * 4 * STG_B)             // 81920 B

__global__ void __launch_bounds__(256, 2)
gemm_mma_kernel(const __half* __restrict__ A,
                const __half* __restrict__ B,
                const float* __restrict__ bias0, const float* __restrict__ bias1,
                const float* __restrict__ bias2,
                __half* __restrict__ Qh,
                __half* __restrict__ Khi, __half* __restrict__ Klo,
                __half* __restrict__ VThi, __half* __restrict__ VTlo,
                float* __restrict__ Cf, int mode)
{
    extern __shared__ __half smraw[];

    const int tid  = threadIdx.x;
    const int wid  = tid >> 5;
    const int lane = tid & 31;
    const int g    = lane >> 2;
    const int t    = lane & 3;
    const int bm   = blockIdx.y;
    const int bn   = blockIdx.x;
    const int wm   = (wid >> 2) * 64;
    const int wn   = (wid & 3) * 32;

    const int arow = (lane & 7) + ((lane >> 3) & 1) * 8;
    const int acol = (lane >> 4) * 8;
    const int brow = (lane & 7) + ((lane >> 4) & 1) * 8;
    const int bcol = ((lane >> 3) & 1) * 8;

    const uint32_t aBase = smem_u32(smraw);
    const uint32_t bBase = aBase + 4 * STG_B;

    const int lrow = tid >> 1;
    const int lco  = (tid & 1) * 16;
    const __half* Ag = A + (size_t)(bm * 128 + lrow) * K2 + lco;
    const __half* Bg = B + (size_t)(bn * 128 + lrow) * K2 + lco;
    const uint32_t dA = aBase + ((uint32_t)lrow * GPAD + lco) * 2;
    const uint32_t dB = bBase + ((uint32_t)lrow * GPAD + lco) * 2;

    auto load_pair = [&](int sp, int k0) {
        CP_ASYNC16(dA + sp * STG_B,            Ag + k0);
        CP_ASYNC16(dA + sp * STG_B + 16,       Ag + k0 + 8);
        CP_ASYNC16(dB + sp * STG_B,            Bg + k0);
        CP_ASYNC16(dB + sp * STG_B + 16,       Bg + k0 + 8);
        CP_ASYNC16(dA + (sp + 1) * STG_B,      Ag + k0 + KCH);
        CP_ASYNC16(dA + (sp + 1) * STG_B + 16, Ag + k0 + KCH + 8);
        CP_ASYNC16(dB + (sp + 1) * STG_B,      Bg + k0 + KCH);
        CP_ASYNC16(dB + (sp + 1) * STG_B + 16, Bg + k0 + KCH + 8);
        CP_COMMIT();
    };

    float acc[4][4][4];
#pragma unroll
    for (int i = 0; i < 4; i++)
#pragma unroll
        for (int j = 0; j < 4; j++)
#pragma unroll
            for (int q = 0; q < 4; q++) acc[i][j][q] = 0.f;

    load_pair(0, 0);
    load_pair(2, 2 * KCH);

    for (int p = 0; p < NPAIR; p++) {
        const int sp = (p & 1) * 2;
        if (p + 1 < NPAIR) { CP_WAIT1(); } else { CP_WAIT0(); }
        __syncthreads();

#pragma unroll
        for (int half = 0; half < 2; half++) {
            const uint32_t aS = aBase + (sp + half) * STG_B;
            const uint32_t bS = bBase + (sp + half) * STG_B;
#pragma unroll
            for (int kk = 0; kk < KCH; kk += 16) {
                uint32_t af[4][4], bf[4][2];
#pragma unroll
                for (int mi = 0; mi < 4; mi++) {
                    uint32_t addr = aS + (((uint32_t)(wm + mi * 16 + arow)) * GPAD + kk + acol) * 2;
                    ldsm_x4(af[mi][0], af[mi][1], af[mi][2], af[mi][3], addr);
                }
#pragma unroll
                for (int np = 0; np < 2; np++) {
                    uint32_t addr = bS + (((uint32_t)(wn + np * 16 + brow)) * GPAD + kk + bcol) * 2;
                    ldsm_x4(bf[2 * np][0], bf[2 * np][1], bf[2 * np + 1][0], bf[2 * np + 1][1], addr);
                }
#pragma unroll
                for (int mi = 0; mi < 4; mi++)
#pragma unroll
                    for (int ni = 0; ni < 4; ni++)
                        mma16816(acc[mi][ni], af[mi], bf[ni]);
            }
        }
        __syncthreads();
        if (p + 2 < NPAIR) load_pair(sp, (p + 2) * 2 * KCH);
    }

    // epilogue
#pragma unroll
    for (int mi = 0; mi < 4; mi++) {
        const int r0 = bm * 128 + wm + mi * 16 + g;
#pragma unroll
        for (int ni = 0; ni < 4; ni++) {
            const int c = bn * 128 + wn + ni * 8 + 2 * t;
            if (mode == 0) {
                const int which = c >> 10;
                const int cc    = c & 1023;
                const float* bp = (which == 0) ? bias0 : (which == 1) ? bias1 : bias2;
                const float bv0 = bp[cc], bv1 = bp[cc + 1];
                float v00 = acc[mi][ni][0] + bv0, v01 = acc[mi][ni][1] + bv1;
                float v10 = acc[mi][ni][2] + bv0, v11 = acc[mi][ni][3] + bv1;
                const int b = r0 >> 11, sq = r0 & 2047;
                const int h = cc >> 6, d = cc & 63;
                if (which == 0) {
                    // Q: hi-only, pre-scaled by 1/sqrt(64)
                    size_t off0 = (((size_t)(b * NHEAD + h) * SEQ) + sq) * HDIM + d;
                    size_t off1 = off0 + 8 * HDIM;
                    *(uint32_t*)(Qh + off0) = packh2(v00 * 0.125f, v01 * 0.125f);
                    *(uint32_t*)(Qh + off1) = packh2(v10 * 0.125f, v11 * 0.125f);
                } else if (which == 1) {
                    size_t off0 = (((size_t)(b * NHEAD + h) * SEQ) + sq) * HDIM + d;
                    size_t off1 = off0 + 8 * HDIM;
                    uint32_t hi0, lo0, hi1, lo1;
                    hilo2h(v00, v01, hi0, lo0);
                    hilo2h(v10, v11, hi1, lo1);
                    *(uint32_t*)(Khi + off0) = hi0;
                    *(uint32_t*)(Klo + off0) = lo0;
                    *(uint32_t*)(Khi + off1) = hi1;
                    *(uint32_t*)(Klo + off1) = lo1;
                } else {
                    size_t offT = (((size_t)(b * NHEAD + h) * HDIM) + d) * SEQ + sq;
                    __half h00, l00, h01, l01, h10, l10, h11, l11;
                    hilo1h(v00, h00, l00);
                    hilo1h(v01, h01, l01);
                    hilo1h(v10, h10, l10);
                    hilo1h(v11, h11, l11);
                    VThi[offT]           = h00;
                    VThi[offT + 8]       = h10;
                    VThi[offT + SEQ]     = h01;
                    VThi[offT + SEQ + 8] = h11;
                    VTlo[offT]           = l00;
                    VTlo[offT + 8]       = l10;
                    VTlo[offT + SEQ]     = l01;
                    VTlo[offT + SEQ + 8] = l11;
                }
            } else {
                const float bv0 = bias0[c], bv1 = bias0[c + 1];
                *(float2*)(Cf + (size_t)r0 * EMB + c) =
                    make_float2(acc[mi][ni][0] + bv0, acc[mi][ni][1] + bv1);
                *(float2*)(Cf + (size_t)(r0 + 8) * EMB + c) =
                    make_float2(acc[mi][ni][2] + bv0, acc[mi][ni][3] + bv1);
            }
        }
    }
}

// ---------------------------------------------------------------------------
// Tensor-core flash attention, fp16 2-term: Br=64, cp.async double-buffer,
// ldmatrix frags, occ 3. grid (SEQ/64, B*H), block 128.
// S = qh·(Khi + Klo) ; O += P_fp16·(Vhi + Vlo).
// ---------------------------------------------------------------------------
#define ASTR 72
#define A_STG (64 * ASTR)
#define ATT_SMEM (8 * A_STG * 2)

__global__ void __launch_bounds__(128, 3)
attn_mma_kernel(const __half* __restrict__ Qh,
                const __half* __restrict__ Khi, const __half* __restrict__ Klo,
                const __half* __restrict__ VThi, const __half* __restrict__ VTlo,
                __half* __restrict__ Out)
{
    extern __shared__ __half sm[];
    __half* sK  = sm;
    __half* sVT = sm + 4 * A_STG;

    const int tid  = threadIdx.x;
    const int wid  = tid >> 5;
    const int lane = tid & 31;
    const int g    = lane >> 2;
    const int t    = lane & 3;
    const int qt   = blockIdx.x;
    const int bh   = blockIdx.y;
    const size_t base  = (size_t)bh * SEQ * HDIM;
    const size_t baseT = (size_t)bh * HDIM * SEQ;

    const int brow = (lane & 7) + ((lane >> 4) & 1) * 8;
    const int bcol = ((lane >> 3) & 1) * 8;

    // --- Stage Q tile (hi only), extract frags ---
#pragma unroll
    for (int i = 0; i < 4; i++) {
        int idx = tid + 128 * i;
        int row = idx >> 3;
        int co  = (idx & 7) * 8;
        *(uint4*)&sK[row * ASTR + co] = *(const uint4*)&Qh[base + (size_t)(qt * 64 + row) * HDIM + co];
    }
    __syncthreads();

    uint32_t qh[4][4];
    {
        const int arow = (lane & 7) + ((lane >> 3) & 1) * 8;
        const int acol = (lane >> 4) * 8;
        const uint32_t qBase = smem_u32(sK);
#pragma unroll
        for (int kj = 0; kj < 4; kj++) {
            uint32_t ah = qBase + (((uint32_t)(wid * 16 + arow)) * ASTR + 16 * kj + acol) * 2;
            ldsm_x4(qh[kj][0], qh[kj][1], qh[kj][2], qh[kj][3], ah);
        }
    }
    __syncthreads();

    const uint32_t sKa  = smem_u32(sK);
    const uint32_t sVTa = smem_u32(sVT);
    auto stage = [&](int st, int kt) {
#pragma unroll
        for (int j = 0; j < 4; j++) {
            int id  = tid + 128 * j;
            int row = id >> 3;
            int co  = (id & 7) * 8;
            uint32_t so = ((uint32_t)row * ASTR + co) * 2;
            CP_ASYNC16(sKa  + (st * 2 + 0) * A_STG * 2 + so, Khi  + base  + (size_t)(kt + row) * HDIM + co);
            CP_ASYNC16(sKa  + (st * 2 + 1) * A_STG * 2 + so, Klo  + base  + (size_t)(kt + row) * HDIM + co);
            CP_ASYNC16(sVTa + (st * 2 + 0) * A_STG * 2 + so, VThi + baseT + (size_t)row * SEQ + kt + co);
            CP_ASYNC16(sVTa + (st * 2 + 1) * A_STG * 2 + so, VTlo + baseT + (size_t)row * SEQ + kt + co);
        }
        CP_COMMIT();
    };

    float o[8][4];
#pragma unroll
    for (int ni = 0; ni < 8; ni++)
#pragma unroll
        for (int j = 0; j < 4; j++) o[ni][j] = 0.f;
    float m0 = -1e30f, m1 = -1e30f, l0 = 0.f, l1 = 0.f;

    stage(0, 0);
    stage(1, 64);

    const int NT = SEQ / 64;
    for (int it = 0; it < NT; it++) {
        const int s = it & 1;
        if (it + 1 < NT) { CP_WAIT1(); } else { CP_WAIT0(); }
        __syncthreads();

        const uint32_t cKhiA = sKa  + (s * 2 + 0) * A_STG * 2;
        const uint32_t cKloA = sKa  + (s * 2 + 1) * A_STG * 2;
        const uint32_t cVhiA = sVTa + (s * 2 + 0) * A_STG * 2;
        const uint32_t cVloA = sVTa + (s * 2 + 1) * A_STG * 2;
        const uint32_t bOff  = ((uint32_t)brow * ASTR + bcol) * 2;

        // --- S = Q K^T (2 terms: Khi + Klo) ---
        float sc[8][4];
#pragma unroll
        for (int ni = 0; ni < 8; ni++)
#pragma unroll
            for (int j = 0; j < 4; j++) sc[ni][j] = 0.f;

#pragma unroll
        for (int kj = 0; kj < 4; kj++) {
#pragma unroll
            for (int np = 0; np < 4; np++) {
                uint32_t off = bOff + ((uint32_t)np * 16 * ASTR + 16 * kj) * 2;
                uint32_t h0[2], h1[2], l0_[2], l1_[2];
                ldsm_x4(h0[0], h0[1], h1[0], h1[1], cKhiA + off);
                ldsm_x4(l0_[0], l0_[1], l1_[0], l1_[1], cKloA + off);
                mma16816(sc[2 * np],     qh[kj], h0);
                mma16816(sc[2 * np],     qh[kj], l0_);
                mma16816(sc[2 * np + 1], qh[kj], h1);
                mma16816(sc[2 * np + 1], qh[kj], l1_);
            }
        }

        // --- online softmax ---
        float mx0 = -1e30f, mx1 = -1e30f;
#pragma unroll
        for (int ni = 0; ni < 8; ni++) {
            mx0 = fmaxf(mx0, fmaxf(sc[ni][0], sc[ni][1]));
            mx1 = fmaxf(mx1, fmaxf(sc[ni][2], sc[ni][3]));
        }
        mx0 = fmaxf(mx0, __shfl_xor_sync(0xffffffff, mx0, 1));
        mx0 = fmaxf(mx0, __shfl_xor_sync(0xffffffff, mx0, 2));
        mx1 = fmaxf(mx1, __shfl_xor_sync(0xffffffff, mx1, 1));
        mx1 = fmaxf(mx1, __shfl_xor_sync(0xffffffff, mx1, 2));

        const float nm0 = fmaxf(m0, mx0);
        const float nm1 = fmaxf(m1, mx1);
        const float rs0 = __expf(m0 - nm0);
        const float rs1 = __expf(m1 - nm1);
        m0 = nm0; m1 = nm1;
        l0 *= rs0; l1 *= rs1;
#pragma unroll
        for (int ni = 0; ni < 8; ni++) {
            o[ni][0] *= rs0; o[ni][1] *= rs0;
            o[ni][2] *= rs1; o[ni][3] *= rs1;
            sc[ni][0] = __expf(sc[ni][0] - m0);
            sc[ni][1] = __expf(sc[ni][1] - m0);
            sc[ni][2] = __expf(sc[ni][2] - m1);
            sc[ni][3] = __expf(sc[ni][3] - m1);
            l0 += sc[ni][0] + sc[ni][1];
            l1 += sc[ni][2] + sc[ni][3];
        }

        // --- O += P V (P fp16, V 2 terms) ---
#pragma unroll
        for (int kj = 0; kj < 4; kj++) {
            uint32_t ah[4];
            ah[0] = packh2(sc[2 * kj][0],     sc[2 * kj][1]);
            ah[1] = packh2(sc[2 * kj][2],     sc[2 * kj][3]);
            ah[2] = packh2(sc[2 * kj + 1][0], sc[2 * kj + 1][1]);
            ah[3] = packh2(sc[2 * kj + 1][2], sc[2 * kj + 1][3]);
#pragma unroll
            for (int np = 0; np < 4; np++) {
                uint32_t off = bOff + ((uint32_t)np * 16 * ASTR + 16 * kj) * 2;
                uint32_t h0[2], h1[2], l0_[2], l1_[2];
                ldsm_x4(h0[0], h0[1], h1[0], h1[1], cVhiA + off);
                ldsm_x4(l0_[0], l0_[1], l1_[0], l1_[1], cVloA + off);
                mma16816(o[2 * np],     ah, h0);
                mma16816(o[2 * np],     ah, l0_);
                mma16816(o[2 * np + 1], ah, h1);
                mma16816(o[2 * np + 1], ah, l1_);
            }
        }

        __syncthreads();
        if (it + 2 < NT) stage(s, (it + 2) * 64);
    }

    // --- finalize: write As = [ah | ah] fp16 ---
    l0 += __shfl_xor_sync(0xffffffff, l0, 1);
    l0 += __shfl_xor_sync(0xffffffff, l0, 2);
    l1 += __shfl_xor_sync(0xffffffff, l1, 1);
    l1 += __shfl_xor_sync(0xffffffff, l1, 2);
    const float inv0 = 1.f / l0;
    const float inv1 = 1.f / l1;

    const int s0 = qt * 64 + wid * 16 + g;
    const int b  = bh >> 4;
    const int h  = bh & 15;
    const size_t row0 = (size_t)(b * SEQ + s0) * K2;
    const size_t row1 = row0 + (size_t)8 * K2;

#pragma unroll
    for (int ni = 0; ni < 8; ni++) {
        const int col = h * 64 + 8 * ni + 2 * t;
        uint32_t p0 = packh2(o[ni][0] * inv0, o[ni][1] * inv0);
        uint32_t p1 = packh2(o[ni][2] * inv1, o[ni][3] * inv1);
        *(uint32_t*)&Out[row0 + col]        = p0;
        *(uint32_t*)&Out[row0 + col + 1024] = p0;
        *(uint32_t*)&Out[row1 + col]        = p1;
        *(uint32_t*)&Out[row1 + col + 1024] = p1;
    }
}

// ---------------------------------------------------------------------------
extern "C" void kernel_launch(void* const* d_in, const int* in_sizes, int n_in,
                              void* d_out, int out_size)
{
    const float* X   = (const float*)d_in[0];
    const float* W_q = (const float*)d_in[1];
    const float* b_q = (const float*)d_in[2];
    const float* W_k = (const float*)d_in[3];
    const float* b_k = (const float*)d_in[4];
    const float* W_v = (const float*)d_in[5];
    const float* b_v = (const float*)d_in[6];
    const float* W_o = (const float*)d_in[7];
    const float* b_o = (const float*)d_in[8];
    float* out = (float*)d_out;

    __half *Qh, *Khi, *Klo, *VThi, *VTlo, *Xs, *Ws, *As;
    cudaGetSymbolAddress((void**)&Qh, g_Qh);
    cudaGetSymbolAddress((void**)&Khi, g_Khi);
    cudaGetSymbolAddress((void**)&Klo, g_Klo);
    cudaGetSymbolAddress((void**)&VThi, g_VThi);
    cudaGetSymbolAddress((void**)&VTlo, g_VTlo);
    cudaGetSymbolAddress((void**)&Xs, g_Xs);
    cudaGetSymbolAddress((void**)&Ws, g_Ws);
    cudaGetSymbolAddress((void**)&As, g_As);

    cudaFuncSetAttribute(gemm_mma_kernel, cudaFuncAttributeMaxDynamicSharedMemorySize, G_SMEM);
    cudaFuncSetAttribute(attn_mma_kernel, cudaFuncAttributeMaxDynamicSharedMemorySize, ATT_SMEM);

    const int cthr = 256;
    split_x_kernel<<<MROWS * EMB / (cthr * 4), cthr>>>(X, Xs);
    dim3 wgrid(EMB * EMB / (cthr * 4), 4);
    split_w_kernel<<<wgrid, cthr>>>(W_q, W_k, W_v, W_o, Ws);

    // fused QKV: N = 3072, tile 128x128, K = 2048
    dim3 qkvgrid(3 * EMB / 128, MROWS / 128);   // (24, 32)
    gemm_mma_kernel<<<qkvgrid, 256, G_SMEM>>>(Xs, Ws, b_q, b_k, b_v,
                                              Qh, Khi, Klo, VThi, VTlo, nullptr, 0);

    dim3 agrid(SEQ / 64, BATCH * NHEAD);
    attn_mma_kernel<<<agrid, 128, ATT_SMEM>>>(Qh, Khi, Klo, VThi, VTlo, As);

    // O-projection: N = 1024, K = 2048
    dim3 ogrid(EMB / 128, MROWS / 128);    // (8, 32)
    gemm_mma_kernel<<<ogrid, 256, G_SMEM>>>(As, Ws + 3 * (size_t)EMB * K2, b_o, nullptr, nullptr,
                                            nullptr, nullptr, nullptr, nullptr, nullptr,
                                            out, 1);
}

// round 15
// speedup vs baseline: 1.8388x; 1.1858x over previous
#include <cuda_runtime.h>
#include <cuda_fp16.h>
#include <stdint.h>
#include <math.h>

#define BATCH   2
#define SEQ     2048
#define EMB     1024
#define NHEAD   16
#define HDIM    64
#define MROWS   (BATCH * SEQ)
#define K2      (2 * EMB)              // 2048: fp16 2-term concat (GEMMs)
#define QKV_ELEMS (BATCH * NHEAD * SEQ * HDIM)

// Scratch (__device__ globals)
__device__ __half g_Qh[QKV_ELEMS];            // Q fp16 (pre-scaled 0.125)
__device__ __half g_Kh[QKV_ELEMS];            // K fp16
__device__ __half g_VTh[QKV_ELEMS];           // V fp16, [B,H,D,S]
__device__ __half g_Xs[(size_t)MROWS * K2];   // [xh | xh]
__device__ __half g_Ws[4][(size_t)EMB * K2];  // [wh | wl]
__device__ __half g_As[(size_t)MROWS * K2];   // [ah | ah]

// ---------------------------------------------------------------------------
__device__ __forceinline__ uint32_t smem_u32(const void* p) {
    uint32_t a;
    asm("{ .reg .u64 t; cvta.to.shared.u64 t, %1; cvt.u32.u64 %0, t; }" : "=r"(a) : "l"(p));
    return a;
}
#define CP_ASYNC16(dst, src) asm volatile("cp.async.cg.shared.global [%0], [%1], 16;" :: "r"(dst), "l"(src))
#define CP_COMMIT()  asm volatile("cp.async.commit_group;" ::: "memory")
#define CP_WAIT1()   asm volatile("cp.async.wait_group 1;" ::: "memory")
#define CP_WAIT0()   asm volatile("cp.async.wait_group 0;" ::: "memory")

__device__ __forceinline__ void ldsm_x4(uint32_t& r0, uint32_t& r1, uint32_t& r2, uint32_t& r3,
                                        uint32_t addr)
{
    asm volatile("ldmatrix.sync.aligned.m8n8.x4.shared.b16 {%0,%1,%2,%3}, [%4];"
        : "=r"(r0), "=r"(r1), "=r"(r2), "=r"(r3) : "r"(addr));
}

__device__ __forceinline__ uint32_t packh2(float x, float y)
{
    __half2 h = __floats2half2_rn(x, y);
    return *(uint32_t*)&h;
}

__device__ __forceinline__ void hilo2h(float x, float y, uint32_t& hi, uint32_t& lo)
{
    __half hx = __float2half_rn(x), hy = __float2half_rn(y);
    __half lx = __float2half_rn(x - __half2float(hx));
    __half ly = __float2half_rn(y - __half2float(hy));
    __half2 h2 = __halves2half2(hx, hy);
    __half2 l2 = __halves2half2(lx, ly);
    hi = *(uint32_t*)&h2;
    lo = *(uint32_t*)&l2;
}

__device__ __forceinline__ void mma16816(float* c, const uint32_t* a, const uint32_t* b)
{
    asm volatile(
        "mma.sync.aligned.m16n8k16.row.col.f32.f16.f16.f32 "
        "{%0,%1,%2,%3}, {%4,%5,%6,%7}, {%8,%9}, {%0,%1,%2,%3};"
        : "+f"(c[0]), "+f"(c[1]), "+f"(c[2]), "+f"(c[3])
        : "r"(a[0]), "r"(a[1]), "r"(a[2]), "r"(a[3]), "r"(b[0]), "r"(b[1]));
}

// ---------------------------------------------------------------------------
// Split conversion kernels
// ---------------------------------------------------------------------------
__global__ void split_x_kernel(const float* __restrict__ in,
                               __half* __restrict__ out)
{
    int idx = (blockIdx.x * blockDim.x + threadIdx.x) * 4;
    int r = idx >> 10;
    int k = idx & 1023;
    float4 x = *(const float4*)(in + idx);
    uint2 hh;
    hh.x = packh2(x.x, x.y);
    hh.y = packh2(x.z, x.w);
    __half* o = out + (size_t)r * K2 + k;
    *(uint2*)(o)        = hh;
    *(uint2*)(o + 1024) = hh;
}

__global__ void split_w_kernel(const float* __restrict__ W0, const float* __restrict__ W1,
                               const float* __restrict__ W2, const float* __restrict__ W3,
                               __half* __restrict__ out)
{
    int w = blockIdx.y;
    const float* in = (w == 0) ? W0 : (w == 1) ? W1 : (w == 2) ? W2 : W3;
    int idx = (blockIdx.x * blockDim.x + threadIdx.x) * 4;
    int r = idx >> 10;
    int k = idx & 1023;
    float4 x = *(const float4*)(in + idx);
    uint32_t h0, l0, h1, l1;
    hilo2h(x.x, x.y, h0, l0);
    hilo2h(x.z, x.w, h1, l1);
    uint2 hh; hh.x = h0; hh.y = h1;
    uint2 ll; ll.x = l0; ll.y = l1;
    __half* o = out + (size_t)w * EMB * K2 + (size_t)r * K2 + k;
    *(uint2*)(o)        = hh;
    *(uint2*)(o + 1024) = ll;
}

// ---------------------------------------------------------------------------
// fp16 HMMA GEMM (R14-exact structure): CTA 128x128, 8 warps, K=2048,
// KCH=32, GPAD=40, 4 stages in chunk-pairs, ldmatrix, occ 2.
// mode 0: fused QKV; Q fp16 scaled [B,H,S,D], K fp16 [B,H,S,D],
//         V fp16 TRANSPOSED [B,H,D,S].
// mode 1: O-projection, fp32 row-major.
// ---------------------------------------------------------------------------
#define GPAD   40
#define KCH    32
#define NPAIR  (K2 / (2 * KCH))            // 32
#define STG_B  (128 * GPAD * 2)            // 10240 B
#define G_SMEM (2 * 4 * STG_B)             // 81920 B

__global__ void __launch_bounds__(256, 2)
gemm_mma_kernel(const __half* __restrict__ A,
                const __half* __restrict__ B,
                const float* __restrict__ bias0, const float* __restrict__ bias1,
                const float* __restrict__ bias2,
                __half* __restrict__ Qh, __half* __restrict__ Kh,
                __half* __restrict__ VTh,
                float* __restrict__ Cf, int mode)
{
    extern __shared__ __half smraw[];

    const int tid  = threadIdx.x;
    const int wid  = tid >> 5;
    const int lane = tid & 31;
    const int g    = lane >> 2;
    const int t    = lane & 3;
    const int bm   = blockIdx.y;
    const int bn   = blockIdx.x;
    const int wm   = (wid >> 2) * 64;
    const int wn   = (wid & 3) * 32;

    const int arow = (lane & 7) + ((lane >> 3) & 1) * 8;
    const int acol = (lane >> 4) * 8;
    const int brow = (lane & 7) + ((lane >> 4) & 1) * 8;
    const int bcol = ((lane >> 3) & 1) * 8;

    const uint32_t aBase = smem_u32(smraw);
    const uint32_t bBase = aBase + 4 * STG_B;

    const int lrow = tid >> 1;
    const int lco  = (tid & 1) * 16;
    const __half* Ag = A + (size_t)(bm * 128 + lrow) * K2 + lco;
    const __half* Bg = B + (size_t)(bn * 128 + lrow) * K2 + lco;
    const uint32_t dA = aBase + ((uint32_t)lrow * GPAD + lco) * 2;
    const uint32_t dB = bBase + ((uint32_t)lrow * GPAD + lco) * 2;

    auto load_pair = [&](int sp, int k0) {
        CP_ASYNC16(dA + sp * STG_B,            Ag + k0);
        CP_ASYNC16(dA + sp * STG_B + 16,       Ag + k0 + 8);
        CP_ASYNC16(dB + sp * STG_B,            Bg + k0);
        CP_ASYNC16(dB + sp * STG_B + 16,       Bg + k0 + 8);
        CP_ASYNC16(dA + (sp + 1) * STG_B,      Ag + k0 + KCH);
        CP_ASYNC16(dA + (sp + 1) * STG_B + 16, Ag + k0 + KCH + 8);
        CP_ASYNC16(dB + (sp + 1) * STG_B,      Bg + k0 + KCH);
        CP_ASYNC16(dB + (sp + 1) * STG_B + 16, Bg + k0 + KCH + 8);
        CP_COMMIT();
    };

    float acc[4][4][4];
#pragma unroll
    for (int i = 0; i < 4; i++)
#pragma unroll
        for (int j = 0; j < 4; j++)
#pragma unroll
            for (int q = 0; q < 4; q++) acc[i][j][q] = 0.f;

    load_pair(0, 0);
    load_pair(2, 2 * KCH);

    for (int p = 0; p < NPAIR; p++) {
        const int sp = (p & 1) * 2;
        if (p + 1 < NPAIR) { CP_WAIT1(); } else { CP_WAIT0(); }
        __syncthreads();

#pragma unroll
        for (int half = 0; half < 2; half++) {
            const uint32_t aS = aBase + (sp + half) * STG_B;
            const uint32_t bS = bBase + (sp + half) * STG_B;
#pragma unroll
            for (int kk = 0; kk < KCH; kk += 16) {
                uint32_t af[4][4], bf[4][2];
#pragma unroll
                for (int mi = 0; mi < 4; mi++) {
                    uint32_t addr = aS + (((uint32_t)(wm + mi * 16 + arow)) * GPAD + kk + acol) * 2;
                    ldsm_x4(af[mi][0], af[mi][1], af[mi][2], af[mi][3], addr);
                }
#pragma unroll
                for (int np = 0; np < 2; np++) {
                    uint32_t addr = bS + (((uint32_t)(wn + np * 16 + brow)) * GPAD + kk + bcol) * 2;
                    ldsm_x4(bf[2 * np][0], bf[2 * np][1], bf[2 * np + 1][0], bf[2 * np + 1][1], addr);
                }
#pragma unroll
                for (int mi = 0; mi < 4; mi++)
#pragma unroll
                    for (int ni = 0; ni < 4; ni++)
                        mma16816(acc[mi][ni], af[mi], bf[ni]);
            }
        }
        __syncthreads();
        if (p + 2 < NPAIR) load_pair(sp, (p + 2) * 2 * KCH);
    }

    // epilogue
#pragma unroll
    for (int mi = 0; mi < 4; mi++) {
        const int r0 = bm * 128 + wm + mi * 16 + g;
#pragma unroll
        for (int ni = 0; ni < 4; ni++) {
            const int c = bn * 128 + wn + ni * 8 + 2 * t;
            if (mode == 0) {
                const int which = c >> 10;
                const int cc    = c & 1023;
                const float* bp = (which == 0) ? bias0 : (which == 1) ? bias1 : bias2;
                const float bv0 = bp[cc], bv1 = bp[cc + 1];
                float v00 = acc[mi][ni][0] + bv0, v01 = acc[mi][ni][1] + bv1;
                float v10 = acc[mi][ni][2] + bv0, v11 = acc[mi][ni][3] + bv1;
                const int b = r0 >> 11, sq = r0 & 2047;
                const int h = cc >> 6, d = cc & 63;
                if (which == 0) {
                    size_t off0 = (((size_t)(b * NHEAD + h) * SEQ) + sq) * HDIM + d;
                    size_t off1 = off0 + 8 * HDIM;
                    *(uint32_t*)(Qh + off0) = packh2(v00 * 0.125f, v01 * 0.125f);
                    *(uint32_t*)(Qh + off1) = packh2(v10 * 0.125f, v11 * 0.125f);
                } else if (which == 1) {
                    size_t off0 = (((size_t)(b * NHEAD + h) * SEQ) + sq) * HDIM + d;
                    size_t off1 = off0 + 8 * HDIM;
                    *(uint32_t*)(Kh + off0) = packh2(v00, v01);
                    *(uint32_t*)(Kh + off1) = packh2(v10, v11);
                } else {
                    size_t offT = (((size_t)(b * NHEAD + h) * HDIM) + d) * SEQ + sq;
                    VTh[offT]           = __float2half_rn(v00);
                    VTh[offT + 8]       = __float2half_rn(v10);
                    VTh[offT + SEQ]     = __float2half_rn(v01);
                    VTh[offT + SEQ + 8] = __float2half_rn(v11);
                }
            } else {
                const float bv0 = bias0[c], bv1 = bias0[c + 1];
                *(float2*)(Cf + (size_t)r0 * EMB + c) =
                    make_float2(acc[mi][ni][0] + bv0, acc[mi][ni][1] + bv1);
                *(float2*)(Cf + (size_t)(r0 + 8) * EMB + c) =
                    make_float2(acc[mi][ni][2] + bv0, acc[mi][ni][3] + bv1);
            }
        }
    }
}

// ---------------------------------------------------------------------------
// Plain-fp16 tensor-core flash attention: Br=64, cp.async double-buffer,
// ldmatrix, occ 4 (smem halved to 36.9 KB, regs freed by dropping lo terms).
// grid (SEQ/64, B*H), block 128.
// ---------------------------------------------------------------------------
#define ASTR 72
#define A_STG (64 * ASTR)
#define ATT_SMEM (4 * A_STG * 2)           // K[2] + VT[2] stages = 36864 B

__global__ void __launch_bounds__(128, 4)
attn_mma_kernel(const __half* __restrict__ Qh,
                const __half* __restrict__ Kh,
                const __half* __restrict__ VTh,
                __half* __restrict__ Out)
{
    extern __shared__ __half sm[];
    __half* sK  = sm;                       // [2][A_STG]
    __half* sVT = sm + 2 * A_STG;           // [2][A_STG]

    const int tid  = threadIdx.x;
    const int wid  = tid >> 5;
    const int lane = tid & 31;
    const int g    = lane >> 2;
    const int t    = lane & 3;
    const int qt   = blockIdx.x;
    const int bh   = blockIdx.y;
    const size_t base  = (size_t)bh * SEQ * HDIM;
    const size_t baseT = (size_t)bh * HDIM * SEQ;

    const int brow = (lane & 7) + ((lane >> 4) & 1) * 8;
    const int bcol = ((lane >> 3) & 1) * 8;

    // --- Stage Q tile, extract frags ---
#pragma unroll
    for (int i = 0; i < 4; i++) {
        int idx = tid + 128 * i;
        int row = idx >> 3;
        int co  = (idx & 7) * 8;
        *(uint4*)&sK[row * ASTR + co] = *(const uint4*)&Qh[base + (size_t)(qt * 64 + row) * HDIM + co];
    }
    __syncthreads();

    uint32_t qh[4][4];
    {
        const int arow = (lane & 7) + ((lane >> 3) & 1) * 8;
        const int acol = (lane >> 4) * 8;
        const uint32_t qBase = smem_u32(sK);
#pragma unroll
        for (int kj = 0; kj < 4; kj++) {
            uint32_t ah = qBase + (((uint32_t)(wid * 16 + arow)) * ASTR + 16 * kj + acol) * 2;
            ldsm_x4(qh[kj][0], qh[kj][1], qh[kj][2], qh[kj][3], ah);
        }
    }
    __syncthreads();

    const uint32_t sKa  = smem_u32(sK);
    const uint32_t sVTa = smem_u32(sVT);
    auto stage = [&](int st, int kt) {
#pragma unroll
        for (int j = 0; j < 4; j++) {
            int id  = tid + 128 * j;
            int row = id >> 3;
            int co  = (id & 7) * 8;
            uint32_t so = ((uint32_t)row * ASTR + co) * 2;
            CP_ASYNC16(sKa  + st * A_STG * 2 + so, Kh  + base  + (size_t)(kt + row) * HDIM + co);
            CP_ASYNC16(sVTa + st * A_STG * 2 + so, VTh + baseT + (size_t)row * SEQ + kt + co);
        }
        CP_COMMIT();
    };

    float o[8][4];
#pragma unroll
    for (int ni = 0; ni < 8; ni++)
#pragma unroll
        for (int j = 0; j < 4; j++) o[ni][j] = 0.f;
    float m0 = -1e30f, m1 = -1e30f, l0 = 0.f, l1 = 0.f;

    stage(0, 0);
    stage(1, 64);

    const int NT = SEQ / 64;
    for (int it = 0; it < NT; it++) {
        const int s = it & 1;
        if (it + 1 < NT) { CP_WAIT1(); } else { CP_WAIT0(); }
        __syncthreads();

        const uint32_t cKA = sKa  + s * A_STG * 2;
        const uint32_t cVA = sVTa + s * A_STG * 2;
        const uint32_t bOff = ((uint32_t)brow * ASTR + bcol) * 2;

        // --- S = Q K^T ---
        float sc[8][4];
#pragma unroll
        for (int ni = 0; ni < 8; ni++)
#pragma unroll
            for (int j = 0; j < 4; j++) sc[ni][j] = 0.f;

#pragma unroll
        for (int kj = 0; kj < 4; kj++) {
#pragma unroll
            for (int np = 0; np < 4; np++) {
                uint32_t off = bOff + ((uint32_t)np * 16 * ASTR + 16 * kj) * 2;
                uint32_t h0[2], h1[2];
                ldsm_x4(h0[0], h0[1], h1[0], h1[1], cKA + off);
                mma16816(sc[2 * np],     qh[kj], h0);
                mma16816(sc[2 * np + 1], qh[kj], h1);
            }
        }

        // --- online softmax ---
        float mx0 = -1e30f, mx1 = -1e30f;
#pragma unroll
        for (int ni = 0; ni < 8; ni++) {
            mx0 = fmaxf(mx0, fmaxf(sc[ni][0], sc[ni][1]));
            mx1 = fmaxf(mx1, fmaxf(sc[ni][2], sc[ni][3]));
        }
        mx0 = fmaxf(mx0, __shfl_xor_sync(0xffffffff, mx0, 1));
        mx0 = fmaxf(mx0, __shfl_xor_sync(0xffffffff, mx0, 2));
        mx1 = fmaxf(mx1, __shfl_xor_sync(0xffffffff, mx1, 1));
        mx1 = fmaxf(mx1, __shfl_xor_sync(0xffffffff, mx1, 2));

        const float nm0 = fmaxf(m0, mx0);
        const float nm1 = fmaxf(m1, mx1);
        const float rs0 = __expf(m0 - nm0);
        const float rs1 = __expf(m1 - nm1);
        m0 = nm0; m1 = nm1;
        l0 *= rs0; l1 *= rs1;
#pragma unroll
        for (int ni = 0; ni < 8; ni++) {
            o[ni][0] *= rs0; o[ni][1] *= rs0;
            o[ni][2] *= rs1; o[ni][3] *= rs1;
            sc[ni][0] = __expf(sc[ni][0] - m0);
            sc[ni][1] = __expf(sc[ni][1] - m0);
            sc[ni][2] = __expf(sc[ni][2] - m1);
            sc[ni][3] = __expf(sc[ni][3] - m1);
            l0 += sc[ni][0] + sc[ni][1];
            l1 += sc[ni][2] + sc[ni][3];
        }

        // --- O += P V ---
#pragma unroll
        for (int kj = 0; kj < 4; kj++) {
            uint32_t ah[4];
            ah[0] = packh2(sc[2 * kj][0],     sc[2 * kj][1]);
            ah[1] = packh2(sc[2 * kj][2],     sc[2 * kj][3]);
            ah[2] = packh2(sc[2 * kj + 1][0], sc[2 * kj + 1][1]);
            ah[3] = packh2(sc[2 * kj + 1][2], sc[2 * kj + 1][3]);
#pragma unroll
            for (int np = 0; np < 4; np++) {
                uint32_t off = bOff + ((uint32_t)np * 16 * ASTR + 16 * kj) * 2;
                uint32_t h0[2], h1[2];
                ldsm_x4(h0[0], h0[1], h1[0], h1[1], cVA + off);
                mma16816(o[2 * np],     ah, h0);
                mma16816(o[2 * np + 1], ah, h1);
            }
        }

        __syncthreads();
        if (it + 2 < NT) stage(s, (it + 2) * 64);
    }

    // --- finalize: write As = [ah | ah] fp16 ---
    l0 += __shfl_xor_sync(0xffffffff, l0, 1);
    l0 += __shfl_xor_sync(0xffffffff, l0, 2);
    l1 += __shfl_xor_sync(0xffffffff, l1, 1);
    l1 += __shfl_xor_sync(0xffffffff, l1, 2);
    const float inv0 = 1.f / l0;
    const float inv1 = 1.f / l1;

    const int s0 = qt * 64 + wid * 16 + g;
    const int b  = bh >> 4;
    const int h  = bh & 15;
    const size_t row0 = (size_t)(b * SEQ + s0) * K2;
    const size_t row1 = row0 + (size_t)8 * K2;

#pragma unroll
    for (int ni = 0; ni < 8; ni++) {
        const int col = h * 64 + 8 * ni + 2 * t;
        uint32_t p0 = packh2(o[ni][0] * inv0, o[ni][1] * inv0);
        uint32_t p1 = packh2(o[ni][2] * inv1, o[ni][3] * inv1);
        *(uint32_t*)&Out[row0 + col]        = p0;
        *(uint32_t*)&Out[row0 + col + 1024] = p0;
        *(uint32_t*)&Out[row1 + col]        = p1;
        *(uint32_t*)&Out[row1 + col + 1024] = p1;
    }
}

// ---------------------------------------------------------------------------
extern "C" void kernel_launch(void* const* d_in, const int* in_sizes, int n_in,
                              void* d_out, int out_size)
{
    const float* X   = (const float*)d_in[0];
    const float* W_q = (const float*)d_in[1];
    const float* b_q = (const float*)d_in[2];
    const float* W_k = (const float*)d_in[3];
    const float* b_k = (const float*)d_in[4];
    const float* W_v = (const float*)d_in[5];
    const float* b_v = (const float*)d_in[6];
    const float* W_o = (const float*)d_in[7];
    const float* b_o = (const float*)d_in[8];
    float* out = (float*)d_out;

    __half *Qh, *Kh, *VTh, *Xs, *Ws, *As;
    cudaGetSymbolAddress((void**)&Qh, g_Qh);
    cudaGetSymbolAddress((void**)&Kh, g_Kh);
    cudaGetSymbolAddress((void**)&VTh, g_VTh);
    cudaGetSymbolAddress((void**)&Xs, g_Xs);
    cudaGetSymbolAddress((void**)&Ws, g_Ws);
    cudaGetSymbolAddress((void**)&As, g_As);

    cudaFuncSetAttribute(gemm_mma_kernel, cudaFuncAttributeMaxDynamicSharedMemorySize, G_SMEM);
    cudaFuncSetAttribute(attn_mma_kernel, cudaFuncAttributeMaxDynamicSharedMemorySize, ATT_SMEM);

    const int cthr = 256;
    split_x_kernel<<<MROWS * EMB / (cthr * 4), cthr>>>(X, Xs);
    dim3 wgrid(EMB * EMB / (cthr * 4), 4);
    split_w_kernel<<<wgrid, cthr>>>(W_q, W_k, W_v, W_o, Ws);

    // fused QKV: N = 3072, tile 128x128, K = 2048
    dim3 qkvgrid(3 * EMB / 128, MROWS / 128);   // (24, 32)
    gemm_mma_kernel<<<qkvgrid, 256, G_SMEM>>>(Xs, Ws, b_q, b_k, b_v,
                                              Qh, Kh, VTh, nullptr, 0);

    dim3 agrid(SEQ / 64, BATCH * NHEAD);
    attn_mma_kernel<<<agrid, 128, ATT_SMEM>>>(Qh, Kh, VTh, As);

    // O-projection: N = 1024, K = 2048
    dim3 ogrid(EMB / 128, MROWS / 128);    // (8, 32)
    gemm_mma_kernel<<<ogrid, 256, G_SMEM>>>(As, Ws + 3 * (size_t)EMB * K2, b_o, nullptr, nullptr,
                                            nullptr, nullptr, nullptr,
                                            out, 1);
}

// round 16
// speedup vs baseline: 2.7543x; 1.4979x over previous
#include <cuda_runtime.h>
#include <cuda_fp16.h>
#include <stdint.h>
#include <math.h>

#define BATCH   2
#define SEQ     2048
#define EMB     1024
#define NHEAD   16
#define HDIM    64
#define MROWS   (BATCH * SEQ)
#define KG      EMB                    // 1024: pure fp16 GEMM K
#define QKV_ELEMS (BATCH * NHEAD * SEQ * HDIM)

// Scratch (__device__ globals)
__device__ __half g_Qh[QKV_ELEMS];            // Q fp16 (pre-scaled 0.125)
__device__ __half g_Kh[QKV_ELEMS];            // K fp16
__device__ __half g_VTh[QKV_ELEMS];           // V fp16, [B,H,D,S]
__device__ __half g_Xs[(size_t)MROWS * KG];   // X fp16
__device__ __half g_Ws[4][(size_t)EMB * KG];  // W fp16
__device__ __half g_As[(size_t)MROWS * KG];   // attn out fp16

// ---------------------------------------------------------------------------
__device__ __forceinline__ uint32_t smem_u32(const void* p) {
    uint32_t a;
    asm("{ .reg .u64 t; cvta.to.shared.u64 t, %1; cvt.u32.u64 %0, t; }" : "=r"(a) : "l"(p));
    return a;
}
#define CP_ASYNC16(dst, src) asm volatile("cp.async.cg.shared.global [%0], [%1], 16;" :: "r"(dst), "l"(src))
#define CP_COMMIT()  asm volatile("cp.async.commit_group;" ::: "memory")
#define CP_WAIT1()   asm volatile("cp.async.wait_group 1;" ::: "memory")
#define CP_WAIT0()   asm volatile("cp.async.wait_group 0;" ::: "memory")

__device__ __forceinline__ void ldsm_x4(uint32_t& r0, uint32_t& r1, uint32_t& r2, uint32_t& r3,
                                        uint32_t addr)
{
    asm volatile("ldmatrix.sync.aligned.m8n8.x4.shared.b16 {%0,%1,%2,%3}, [%4];"
        : "=r"(r0), "=r"(r1), "=r"(r2), "=r"(r3) : "r"(addr));
}

__device__ __forceinline__ uint32_t packh2(float x, float y)
{
    __half2 h = __floats2half2_rn(x, y);
    return *(uint32_t*)&h;
}

__device__ __forceinline__ void mma16816(float* c, const uint32_t* a, const uint32_t* b)
{
    asm volatile(
        "mma.sync.aligned.m16n8k16.row.col.f32.f16.f16.f32 "
        "{%0,%1,%2,%3}, {%4,%5,%6,%7}, {%8,%9}, {%0,%1,%2,%3};"
        : "+f"(c[0]), "+f"(c[1]), "+f"(c[2]), "+f"(c[3])
        : "r"(a[0]), "r"(a[1]), "r"(a[2]), "r"(a[3]), "r"(b[0]), "r"(b[1]));
}

// ---------------------------------------------------------------------------
// Conversion kernels: fp32 -> fp16 (plain)
// ---------------------------------------------------------------------------
__global__ void conv_x_kernel(const float* __restrict__ in,
                              __half* __restrict__ out)
{
    int idx = (blockIdx.x * blockDim.x + threadIdx.x) * 4;
    float4 x = *(const float4*)(in + idx);
    uint2 hh;
    hh.x = packh2(x.x, x.y);
    hh.y = packh2(x.z, x.w);
    *(uint2*)(out + idx) = hh;
}

__global__ void conv_w_kernel(const float* __restrict__ W0, const float* __restrict__ W1,
                              const float* __restrict__ W2, const float* __restrict__ W3,
                              __half* __restrict__ out)
{
    int w = blockIdx.y;
    const float* in = (w == 0) ? W0 : (w == 1) ? W1 : (w == 2) ? W2 : W3;
    int idx = (blockIdx.x * blockDim.x + threadIdx.x) * 4;
    float4 x = *(const float4*)(in + idx);
    uint2 hh;
    hh.x = packh2(x.x, x.y);
    hh.y = packh2(x.z, x.w);
    *(uint2*)(out + (size_t)w * EMB * KG + idx) = hh;
}

// ---------------------------------------------------------------------------
// fp16 HMMA GEMM: CTA 128x128, 8 warps, K=1024, KCH=32, GPAD=40,
// 4 stages in chunk-pairs, ldmatrix, occ 2.  (R15 structure, K halved.)
// mode 0: fused QKV; Q fp16 scaled [B,H,S,D], K fp16 [B,H,S,D],
//         V fp16 TRANSPOSED [B,H,D,S].
// mode 1: O-projection, fp32 row-major.
// ---------------------------------------------------------------------------
#define GPAD   40
#define KCH    32
#define NPAIR  (KG / (2 * KCH))            // 16
#define STG_B  (128 * GPAD * 2)            // 10240 B
#define G_SMEM (2 * 4 * STG_B)             // 81920 B

__global__ void __launch_bounds__(256, 2)
gemm_mma_kernel(const __half* __restrict__ A,
                const __half* __restrict__ B,
                const float* __restrict__ bias0, const float* __restrict__ bias1,
                const float* __restrict__ bias2,
                __half* __restrict__ Qh, __half* __restrict__ Kh,
                __half* __restrict__ VTh,
                float* __restrict__ Cf, int mode)
{
    extern __shared__ __half smraw[];

    const int tid  = threadIdx.x;
    const int wid  = tid >> 5;
    const int lane = tid & 31;
    const int g    = lane >> 2;
    const int t    = lane & 3;
    const int bm   = blockIdx.y;
    const int bn   = blockIdx.x;
    const int wm   = (wid >> 2) * 64;
    const int wn   = (wid & 3) * 32;

    const int arow = (lane & 7) + ((lane >> 3) & 1) * 8;
    const int acol = (lane >> 4) * 8;
    const int brow = (lane & 7) + ((lane >> 4) & 1) * 8;
    const int bcol = ((lane >> 3) & 1) * 8;

    const uint32_t aBase = smem_u32(smraw);
    const uint32_t bBase = aBase + 4 * STG_B;

    const int lrow = tid >> 1;
    const int lco  = (tid & 1) * 16;
    const __half* Ag = A + (size_t)(bm * 128 + lrow) * KG + lco;
    const __half* Bg = B + (size_t)(bn * 128 + lrow) * KG + lco;
    const uint32_t dA = aBase + ((uint32_t)lrow * GPAD + lco) * 2;
    const uint32_t dB = bBase + ((uint32_t)lrow * GPAD + lco) * 2;

    auto load_pair = [&](int sp, int k0) {
        CP_ASYNC16(dA + sp * STG_B,            Ag + k0);
        CP_ASYNC16(dA + sp * STG_B + 16,       Ag + k0 + 8);
        CP_ASYNC16(dB + sp * STG_B,            Bg + k0);
        CP_ASYNC16(dB + sp * STG_B + 16,       Bg + k0 + 8);
        CP_ASYNC16(dA + (sp + 1) * STG_B,      Ag + k0 + KCH);
        CP_ASYNC16(dA + (sp + 1) * STG_B + 16, Ag + k0 + KCH + 8);
        CP_ASYNC16(dB + (sp + 1) * STG_B,      Bg + k0 + KCH);
        CP_ASYNC16(dB + (sp + 1) * STG_B + 16, Bg + k0 + KCH + 8);
        CP_COMMIT();
    };

    float acc[4][4][4];
#pragma unroll
    for (int i = 0; i < 4; i++)
#pragma unroll
        for (int j = 0; j < 4; j++)
#pragma unroll
            for (int q = 0; q < 4; q++) acc[i][j][q] = 0.f;

    load_pair(0, 0);
    load_pair(2, 2 * KCH);

    for (int p = 0; p < NPAIR; p++) {
        const int sp = (p & 1) * 2;
        if (p + 1 < NPAIR) { CP_WAIT1(); } else { CP_WAIT0(); }
        __syncthreads();

#pragma unroll
        for (int half = 0; half < 2; half++) {
            const uint32_t aS = aBase + (sp + half) * STG_B;
            const uint32_t bS = bBase + (sp + half) * STG_B;
#pragma unroll
            for (int kk = 0; kk < KCH; kk += 16) {
                uint32_t af[4][4], bf[4][2];
#pragma unroll
                for (int mi = 0; mi < 4; mi++) {
                    uint32_t addr = aS + (((uint32_t)(wm + mi * 16 + arow)) * GPAD + kk + acol) * 2;
                    ldsm_x4(af[mi][0], af[mi][1], af[mi][2], af[mi][3], addr);
                }
#pragma unroll
                for (int np = 0; np < 2; np++) {
                    uint32_t addr = bS + (((uint32_t)(wn + np * 16 + brow)) * GPAD + kk + bcol) * 2;
                    ldsm_x4(bf[2 * np][0], bf[2 * np][1], bf[2 * np + 1][0], bf[2 * np + 1][1], addr);
                }
#pragma unroll
                for (int mi = 0; mi < 4; mi++)
#pragma unroll
                    for (int ni = 0; ni < 4; ni++)
                        mma16816(acc[mi][ni], af[mi], bf[ni]);
            }
        }
        __syncthreads();
        if (p + 2 < NPAIR) load_pair(sp, (p + 2) * 2 * KCH);
    }

    // epilogue
#pragma unroll
    for (int mi = 0; mi < 4; mi++) {
        const int r0 = bm * 128 + wm + mi * 16 + g;
#pragma unroll
        for (int ni = 0; ni < 4; ni++) {
            const int c = bn * 128 + wn + ni * 8 + 2 * t;
            if (mode == 0) {
                const int which = c >> 10;
                const int cc    = c & 1023;
                const float* bp = (which == 0) ? bias0 : (which == 1) ? bias1 : bias2;
                const float bv0 = bp[cc], bv1 = bp[cc + 1];
                float v00 = acc[mi][ni][0] + bv0, v01 = acc[mi][ni][1] + bv1;
                float v10 = acc[mi][ni][2] + bv0, v11 = acc[mi][ni][3] + bv1;
                const int b = r0 >> 11, sq = r0 & 2047;
                const int h = cc >> 6, d = cc & 63;
                if (which == 0) {
                    size_t off0 = (((size_t)(b * NHEAD + h) * SEQ) + sq) * HDIM + d;
                    size_t off1 = off0 + 8 * HDIM;
                    *(uint32_t*)(Qh + off0) = packh2(v00 * 0.125f, v01 * 0.125f);
                    *(uint32_t*)(Qh + off1) = packh2(v10 * 0.125f, v11 * 0.125f);
                } else if (which == 1) {
                    size_t off0 = (((size_t)(b * NHEAD + h) * SEQ) + sq) * HDIM + d;
                    size_t off1 = off0 + 8 * HDIM;
                    *(uint32_t*)(Kh + off0) = packh2(v00, v01);
                    *(uint32_t*)(Kh + off1) = packh2(v10, v11);
                } else {
                    size_t offT = (((size_t)(b * NHEAD + h) * HDIM) + d) * SEQ + sq;
                    VTh[offT]           = __float2half_rn(v00);
                    VTh[offT + 8]       = __float2half_rn(v10);
                    VTh[offT + SEQ]     = __float2half_rn(v01);
                    VTh[offT + SEQ + 8] = __float2half_rn(v11);
                }
            } else {
                const float bv0 = bias0[c], bv1 = bias0[c + 1];
                *(float2*)(Cf + (size_t)r0 * EMB + c) =
                    make_float2(acc[mi][ni][0] + bv0, acc[mi][ni][1] + bv1);
                *(float2*)(Cf + (size_t)(r0 + 8) * EMB + c) =
                    make_float2(acc[mi][ni][2] + bv0, acc[mi][ni][3] + bv1);
            }
        }
    }
}

// ---------------------------------------------------------------------------
// Plain-fp16 tensor-core flash attention (R15-exact): Br=64, cp.async
// double-buffer, ldmatrix, occ 4. grid (SEQ/64, B*H), block 128.
// Output written ONCE to As (fp16, row stride 1024).
// ---------------------------------------------------------------------------
#define ASTR 72
#define A_STG (64 * ASTR)
#define ATT_SMEM (4 * A_STG * 2)           // 36864 B

__global__ void __launch_bounds__(128, 4)
attn_mma_kernel(const __half* __restrict__ Qh,
                const __half* __restrict__ Kh,
                const __half* __restrict__ VTh,
                __half* __restrict__ Out)
{
    extern __shared__ __half sm[];
    __half* sK  = sm;
    __half* sVT = sm + 2 * A_STG;

    const int tid  = threadIdx.x;
    const int wid  = tid >> 5;
    const int lane = tid & 31;
    const int g    = lane >> 2;
    const int t    = lane & 3;
    const int qt   = blockIdx.x;
    const int bh   = blockIdx.y;
    const size_t base  = (size_t)bh * SEQ * HDIM;
    const size_t baseT = (size_t)bh * HDIM * SEQ;

    const int brow = (lane & 7) + ((lane >> 4) & 1) * 8;
    const int bcol = ((lane >> 3) & 1) * 8;

#pragma unroll
    for (int i = 0; i < 4; i++) {
        int idx = tid + 128 * i;
        int row = idx >> 3;
        int co  = (idx & 7) * 8;
        *(uint4*)&sK[row * ASTR + co] = *(const uint4*)&Qh[base + (size_t)(qt * 64 + row) * HDIM + co];
    }
    __syncthreads();

    uint32_t qh[4][4];
    {
        const int arow = (lane & 7) + ((lane >> 3) & 1) * 8;
        const int acol = (lane >> 4) * 8;
        const uint32_t qBase = smem_u32(sK);
#pragma unroll
        for (int kj = 0; kj < 4; kj++) {
            uint32_t ah = qBase + (((uint32_t)(wid * 16 + arow)) * ASTR + 16 * kj + acol) * 2;
            ldsm_x4(qh[kj][0], qh[kj][1], qh[kj][2], qh[kj][3], ah);
        }
    }
    __syncthreads();

    const uint32_t sKa  = smem_u32(sK);
    const uint32_t sVTa = smem_u32(sVT);
    auto stage = [&](int st, int kt) {
#pragma unroll
        for (int j = 0; j < 4; j++) {
            int id  = tid + 128 * j;
            int row = id >> 3;
            int co  = (id & 7) * 8;
            uint32_t so = ((uint32_t)row * ASTR + co) * 2;
            CP_ASYNC16(sKa  + st * A_STG * 2 + so, Kh  + base  + (size_t)(kt + row) * HDIM + co);
            CP_ASYNC16(sVTa + st * A_STG * 2 + so, VTh + baseT + (size_t)row * SEQ + kt + co);
        }
        CP_COMMIT();
    };

    float o[8][4];
#pragma unroll
    for (int ni = 0; ni < 8; ni++)
#pragma unroll
        for (int j = 0; j < 4; j++) o[ni][j] = 0.f;
    float m0 = -1e30f, m1 = -1e30f, l0 = 0.f, l1 = 0.f;

    stage(0, 0);
    stage(1, 64);

    const int NT = SEQ / 64;
    for (int it = 0; it < NT; it++) {
        const int s = it & 1;
        if (it + 1 < NT) { CP_WAIT1(); } else { CP_WAIT0(); }
        __syncthreads();

        const uint32_t cKA = sKa  + s * A_STG * 2;
        const uint32_t cVA = sVTa + s * A_STG * 2;
        const uint32_t bOff = ((uint32_t)brow * ASTR + bcol) * 2;

        float sc[8][4];
#pragma unroll
        for (int ni = 0; ni < 8; ni++)
#pragma unroll
            for (int j = 0; j < 4; j++) sc[ni][j] = 0.f;

#pragma unroll
        for (int kj = 0; kj < 4; kj++) {
#pragma unroll
            for (int np = 0; np < 4; np++) {
                uint32_t off = bOff + ((uint32_t)np * 16 * ASTR + 16 * kj) * 2;
                uint32_t h0[2], h1[2];
                ldsm_x4(h0[0], h0[1], h1[0], h1[1], cKA + off);
                mma16816(sc[2 * np],     qh[kj], h0);
                mma16816(sc[2 * np + 1], qh[kj], h1);
            }
        }

        float mx0 = -1e30f, mx1 = -1e30f;
#pragma unroll
        for (int ni = 0; ni < 8; ni++) {
            mx0 = fmaxf(mx0, fmaxf(sc[ni][0], sc[ni][1]));
            mx1 = fmaxf(mx1, fmaxf(sc[ni][2], sc[ni][3]));
        }
        mx0 = fmaxf(mx0, __shfl_xor_sync(0xffffffff, mx0, 1));
        mx0 = fmaxf(mx0, __shfl_xor_sync(0xffffffff, mx0, 2));
        mx1 = fmaxf(mx1, __shfl_xor_sync(0xffffffff, mx1, 1));
        mx1 = fmaxf(mx1, __shfl_xor_sync(0xffffffff, mx1, 2));

        const float nm0 = fmaxf(m0, mx0);
        const float nm1 = fmaxf(m1, mx1);
        const float rs0 = __expf(m0 - nm0);
        const float rs1 = __expf(m1 - nm1);
        m0 = nm0; m1 = nm1;
        l0 *= rs0; l1 *= rs1;
#pragma unroll
        for (int ni = 0; ni < 8; ni++) {
            o[ni][0] *= rs0; o[ni][1] *= rs0;
            o[ni][2] *= rs1; o[ni][3] *= rs1;
            sc[ni][0] = __expf(sc[ni][0] - m0);
            sc[ni][1] = __expf(sc[ni][1] - m0);
            sc[ni][2] = __expf(sc[ni][2] - m1);
            sc[ni][3] = __expf(sc[ni][3] - m1);
            l0 += sc[ni][0] + sc[ni][1];
            l1 += sc[ni][2] + sc[ni][3];
        }

#pragma unroll
        for (int kj = 0; kj < 4; kj++) {
            uint32_t ah[4];
            ah[0] = packh2(sc[2 * kj][0],     sc[2 * kj][1]);
            ah[1] = packh2(sc[2 * kj][2],     sc[2 * kj][3]);
            ah[2] = packh2(sc[2 * kj + 1][0], sc[2 * kj + 1][1]);
            ah[3] = packh2(sc[2 * kj + 1][2], sc[2 * kj + 1][3]);
#pragma unroll
            for (int np = 0; np < 4; np++) {
                uint32_t off = bOff + ((uint32_t)np * 16 * ASTR + 16 * kj) * 2;
                uint32_t h0[2], h1[2];
                ldsm_x4(h0[0], h0[1], h1[0], h1[1], cVA + off);
                mma16816(o[2 * np],     ah, h0);
                mma16816(o[2 * np + 1], ah, h1);
            }
        }

        __syncthreads();
        if (it + 2 < NT) stage(s, (it + 2) * 64);
    }

    // --- finalize: write As fp16 (single copy) ---
    l0 += __shfl_xor_sync(0xffffffff, l0, 1);
    l0 += __shfl_xor_sync(0xffffffff, l0, 2);
    l1 += __shfl_xor_sync(0xffffffff, l1, 1);
    l1 += __shfl_xor_sync(0xffffffff, l1, 2);
    const float inv0 = 1.f / l0;
    const float inv1 = 1.f / l1;

    const int s0 = qt * 64 + wid * 16 + g;
    const int b  = bh >> 4;
    const int h  = bh & 15;
    const size_t row0 = (size_t)(b * SEQ + s0) * KG;
    const size_t row1 = row0 + (size_t)8 * KG;

#pragma unroll
    for (int ni = 0; ni < 8; ni++) {
        const int col = h * 64 + 8 * ni + 2 * t;
        *(uint32_t*)&Out[row0 + col] = packh2(o[ni][0] * inv0, o[ni][1] * inv0);
        *(uint32_t*)&Out[row1 + col] = packh2(o[ni][2] * inv1, o[ni][3] * inv1);
    }
}

// ---------------------------------------------------------------------------
extern "C" void kernel_launch(void* const* d_in, const int* in_sizes, int n_in,
                              void* d_out, int out_size)
{
    const float* X   = (const float*)d_in[0];
    const float* W_q = (const float*)d_in[1];
    const float* b_q = (const float*)d_in[2];
    const float* W_k = (const float*)d_in[3];
    const float* b_k = (const float*)d_in[4];
    const float* W_v = (const float*)d_in[5];
    const float* b_v = (const float*)d_in[6];
    const float* W_o = (const float*)d_in[7];
    const float* b_o = (const float*)d_in[8];
    float* out = (float*)d_out;

    __half *Qh, *Kh, *VTh, *Xs, *Ws, *As;
    cudaGetSymbolAddress((void**)&Qh, g_Qh);
    cudaGetSymbolAddress((void**)&Kh, g_Kh);
    cudaGetSymbolAddress((void**)&VTh, g_VTh);
    cudaGetSymbolAddress((void**)&Xs, g_Xs);
    cudaGetSymbolAddress((void**)&Ws, g_Ws);
    cudaGetSymbolAddress((void**)&As, g_As);

    cudaFuncSetAttribute(gemm_mma_kernel, cudaFuncAttributeMaxDynamicSharedMemorySize, G_SMEM);
    cudaFuncSetAttribute(attn_mma_kernel, cudaFuncAttributeMaxDynamicSharedMemorySize, ATT_SMEM);

    const int cthr = 256;
    conv_x_kernel<<<MROWS * EMB / (cthr * 4), cthr>>>(X, Xs);
    dim3 wgrid(EMB * EMB / (cthr * 4), 4);
    conv_w_kernel<<<wgrid, cthr>>>(W_q, W_k, W_v, W_o, Ws);

    // fused QKV: N = 3072, tile 128x128, K = 1024
    dim3 qkvgrid(3 * EMB / 128, MROWS / 128);   // (24, 32)
    gemm_mma_kernel<<<qkvgrid, 256, G_SMEM>>>(Xs, Ws, b_q, b_k, b_v,
                                              Qh, Kh, VTh, nullptr, 0);

    dim3 agrid(SEQ / 64, BATCH * NHEAD);
    attn_mma_kernel<<<agrid, 128, ATT_SMEM>>>(Qh, Kh, VTh, As);

    // O-projection: N = 1024, K = 1024
    dim3 ogrid(EMB / 128, MROWS / 128);    // (8, 32)
    gemm_mma_kernel<<<ogrid, 256, G_SMEM>>>(As, Ws + 3 * (size_t)EMB * KG, b_o, nullptr, nullptr,
                                            nullptr, nullptr, nullptr,
                                            out, 1);
}

// round 17
// speedup vs baseline: 2.8262x; 1.0261x over previous
#include <cuda_runtime.h>
#include <cuda_fp16.h>
#include <stdint.h>
#include <math.h>

#define BATCH   2
#define SEQ     2048
#define EMB     1024
#define NHEAD   16
#define HDIM    64
#define MROWS   (BATCH * SEQ)
#define KG      EMB                    // 1024: pure fp16 GEMM K
#define QKV_ELEMS (BATCH * NHEAD * SEQ * HDIM)

// Q pre-scale: (1/sqrt(64)) * log2(e)  -> logits arrive in log2 domain
#define QSCALE 0.18033688011112042f

// Scratch (__device__ globals)
__device__ __half g_Qh[QKV_ELEMS];            // Q fp16 (pre-scaled)
__device__ __half g_Kh[QKV_ELEMS];            // K fp16
__device__ __half g_VTh[QKV_ELEMS];           // V fp16, [B,H,D,S]
__device__ __half g_Xs[(size_t)MROWS * KG];   // X fp16
__device__ __half g_Ws[4][(size_t)EMB * KG];  // W fp16
__device__ __half g_As[(size_t)MROWS * KG];   // attn out fp16

// ---------------------------------------------------------------------------
__device__ __forceinline__ uint32_t smem_u32(const void* p) {
    uint32_t a;
    asm("{ .reg .u64 t; cvta.to.shared.u64 t, %1; cvt.u32.u64 %0, t; }" : "=r"(a) : "l"(p));
    return a;
}
#define CP_ASYNC16(dst, src) asm volatile("cp.async.cg.shared.global [%0], [%1], 16;" :: "r"(dst), "l"(src))
#define CP_COMMIT()  asm volatile("cp.async.commit_group;" ::: "memory")
#define CP_WAIT1()   asm volatile("cp.async.wait_group 1;" ::: "memory")
#define CP_WAIT0()   asm volatile("cp.async.wait_group 0;" ::: "memory")

__device__ __forceinline__ void ldsm_x4(uint32_t& r0, uint32_t& r1, uint32_t& r2, uint32_t& r3,
                                        uint32_t addr)
{
    asm volatile("ldmatrix.sync.aligned.m8n8.x4.shared.b16 {%0,%1,%2,%3}, [%4];"
        : "=r"(r0), "=r"(r1), "=r"(r2), "=r"(r3) : "r"(addr));
}

__device__ __forceinline__ uint32_t packh2(float x, float y)
{
    __half2 h = __floats2half2_rn(x, y);
    return *(uint32_t*)&h;
}

__device__ __forceinline__ float ex2f(float x)
{
    float y;
    asm("ex2.approx.f32 %0, %1;" : "=f"(y) : "f"(x));
    return y;
}

__device__ __forceinline__ void mma16816(float* c, const uint32_t* a, const uint32_t* b)
{
    asm volatile(
        "mma.sync.aligned.m16n8k16.row.col.f32.f16.f16.f32 "
        "{%0,%1,%2,%3}, {%4,%5,%6,%7}, {%8,%9}, {%0,%1,%2,%3};"
        : "+f"(c[0]), "+f"(c[1]), "+f"(c[2]), "+f"(c[3])
        : "r"(a[0]), "r"(a[1]), "r"(a[2]), "r"(a[3]), "r"(b[0]), "r"(b[1]));
}

// ---------------------------------------------------------------------------
// Fused conversion: fp32 -> fp16. grid.y: 0 = X (4M elems), 1..4 = W[0..3].
// ---------------------------------------------------------------------------
__global__ void conv_kernel(const float* __restrict__ X,
                            const float* __restrict__ W0, const float* __restrict__ W1,
                            const float* __restrict__ W2, const float* __restrict__ W3,
                            __half* __restrict__ Xs, __half* __restrict__ Ws)
{
    int src = blockIdx.y;
    int idx = (blockIdx.x * blockDim.x + threadIdx.x) * 4;
    const float* in;
    __half* out;
    if (src == 0) { in = X; out = Xs; }
    else {
        in  = (src == 1) ? W0 : (src == 2) ? W1 : (src == 3) ? W2 : W3;
        out = Ws + (size_t)(src - 1) * EMB * KG;
        if (idx >= EMB * KG) return;
    }
    float4 x = *(const float4*)(in + idx);
    uint2 hh;
    hh.x = packh2(x.x, x.y);
    hh.y = packh2(x.z, x.w);
    *(uint2*)(out + idx) = hh;
}

// ---------------------------------------------------------------------------
// fp16 HMMA GEMM (R16-exact): CTA 128x128, 8 warps, K=1024, KCH=32, GPAD=40,
// 4 stages in chunk-pairs, ldmatrix, occ 2.
// mode 0: fused QKV; Q fp16 scaled (log2 domain) [B,H,S,D], K fp16 [B,H,S,D],
//         V fp16 TRANSPOSED [B,H,D,S].
// mode 1: O-projection, fp32 row-major.
// ---------------------------------------------------------------------------
#define GPAD   40
#define KCH    32
#define NPAIR  (KG / (2 * KCH))            // 16
#define STG_B  (128 * GPAD * 2)            // 10240 B
#define G_SMEM (2 * 4 * STG_B)             // 81920 B

__global__ void __launch_bounds__(256, 2)
gemm_mma_kernel(const __half* __restrict__ A,
                const __half* __restrict__ B,
                const float* __restrict__ bias0, const float* __restrict__ bias1,
                const float* __restrict__ bias2,
                __half* __restrict__ Qh, __half* __restrict__ Kh,
                __half* __restrict__ VTh,
                float* __restrict__ Cf, int mode)
{
    extern __shared__ __half smraw[];

    const int tid  = threadIdx.x;
    const int wid  = tid >> 5;
    const int lane = tid & 31;
    const int g    = lane >> 2;
    const int t    = lane & 3;
    const int bm   = blockIdx.y;
    const int bn   = blockIdx.x;
    const int wm   = (wid >> 2) * 64;
    const int wn   = (wid & 3) * 32;

    const int arow = (lane & 7) + ((lane >> 3) & 1) * 8;
    const int acol = (lane >> 4) * 8;
    const int brow = (lane & 7) + ((lane >> 4) & 1) * 8;
    const int bcol = ((lane >> 3) & 1) * 8;

    const uint32_t aBase = smem_u32(smraw);
    const uint32_t bBase = aBase + 4 * STG_B;

    const int lrow = tid >> 1;
    const int lco  = (tid & 1) * 16;
    const __half* Ag = A + (size_t)(bm * 128 + lrow) * KG + lco;
    const __half* Bg = B + (size_t)(bn * 128 + lrow) * KG + lco;
    const uint32_t dA = aBase + ((uint32_t)lrow * GPAD + lco) * 2;
    const uint32_t dB = bBase + ((uint32_t)lrow * GPAD + lco) * 2;

    auto load_pair = [&](int sp, int k0) {
        CP_ASYNC16(dA + sp * STG_B,            Ag + k0);
        CP_ASYNC16(dA + sp * STG_B + 16,       Ag + k0 + 8);
        CP_ASYNC16(dB + sp * STG_B,            Bg + k0);
        CP_ASYNC16(dB + sp * STG_B + 16,       Bg + k0 + 8);
        CP_ASYNC16(dA + (sp + 1) * STG_B,      Ag + k0 + KCH);
        CP_ASYNC16(dA + (sp + 1) * STG_B + 16, Ag + k0 + KCH + 8);
        CP_ASYNC16(dB + (sp + 1) * STG_B,      Bg + k0 + KCH);
        CP_ASYNC16(dB + (sp + 1) * STG_B + 16, Bg + k0 + KCH + 8);
        CP_COMMIT();
    };

    float acc[4][4][4];
#pragma unroll
    for (int i = 0; i < 4; i++)
#pragma unroll
        for (int j = 0; j < 4; j++)
#pragma unroll
            for (int q = 0; q < 4; q++) acc[i][j][q] = 0.f;

    load_pair(0, 0);
    load_pair(2, 2 * KCH);

    for (int p = 0; p < NPAIR; p++) {
        const int sp = (p & 1) * 2;
        if (p + 1 < NPAIR) { CP_WAIT1(); } else { CP_WAIT0(); }
        __syncthreads();

#pragma unroll
        for (int half = 0; half < 2; half++) {
            const uint32_t aS = aBase + (sp + half) * STG_B;
            const uint32_t bS = bBase + (sp + half) * STG_B;
#pragma unroll
            for (int kk = 0; kk < KCH; kk += 16) {
                uint32_t af[4][4], bf[4][2];
#pragma unroll
                for (int mi = 0; mi < 4; mi++) {
                    uint32_t addr = aS + (((uint32_t)(wm + mi * 16 + arow)) * GPAD + kk + acol) * 2;
                    ldsm_x4(af[mi][0], af[mi][1], af[mi][2], af[mi][3], addr);
                }
#pragma unroll
                for (int np = 0; np < 2; np++) {
                    uint32_t addr = bS + (((uint32_t)(wn + np * 16 + brow)) * GPAD + kk + bcol) * 2;
                    ldsm_x4(bf[2 * np][0], bf[2 * np][1], bf[2 * np + 1][0], bf[2 * np + 1][1], addr);
                }
#pragma unroll
                for (int mi = 0; mi < 4; mi++)
#pragma unroll
                    for (int ni = 0; ni < 4; ni++)
                        mma16816(acc[mi][ni], af[mi], bf[ni]);
            }
        }
        __syncthreads();
        if (p + 2 < NPAIR) load_pair(sp, (p + 2) * 2 * KCH);
    }

    // epilogue
#pragma unroll
    for (int mi = 0; mi < 4; mi++) {
        const int r0 = bm * 128 + wm + mi * 16 + g;
#pragma unroll
        for (int ni = 0; ni < 4; ni++) {
            const int c = bn * 128 + wn + ni * 8 + 2 * t;
            if (mode == 0) {
                const int which = c >> 10;
                const int cc    = c & 1023;
                const float* bp = (which == 0) ? bias0 : (which == 1) ? bias1 : bias2;
                const float bv0 = bp[cc], bv1 = bp[cc + 1];
                float v00 = acc[mi][ni][0] + bv0, v01 = acc[mi][ni][1] + bv1;
                float v10 = acc[mi][ni][2] + bv0, v11 = acc[mi][ni][3] + bv1;
                const int b = r0 >> 11, sq = r0 & 2047;
                const int h = cc >> 6, d = cc & 63;
                if (which == 0) {
                    size_t off0 = (((size_t)(b * NHEAD + h) * SEQ) + sq) * HDIM + d;
                    size_t off1 = off0 + 8 * HDIM;
                    *(uint32_t*)(Qh + off0) = packh2(v00 * QSCALE, v01 * QSCALE);
                    *(uint32_t*)(Qh + off1) = packh2(v10 * QSCALE, v11 * QSCALE);
                } else if (which == 1) {
                    size_t off0 = (((size_t)(b * NHEAD + h) * SEQ) + sq) * HDIM + d;
                    size_t off1 = off0 + 8 * HDIM;
                    *(uint32_t*)(Kh + off0) = packh2(v00, v01);
                    *(uint32_t*)(Kh + off1) = packh2(v10, v11);
                } else {
                    size_t offT = (((size_t)(b * NHEAD + h) * HDIM) + d) * SEQ + sq;
                    VTh[offT]           = __float2half_rn(v00);
                    VTh[offT + 8]       = __float2half_rn(v10);
                    VTh[offT + SEQ]     = __float2half_rn(v01);
                    VTh[offT + SEQ + 8] = __float2half_rn(v11);
                }
            } else {
                const float bv0 = bias0[c], bv1 = bias0[c + 1];
                *(float2*)(Cf + (size_t)r0 * EMB + c) =
                    make_float2(acc[mi][ni][0] + bv0, acc[mi][ni][1] + bv1);
                *(float2*)(Cf + (size_t)(r0 + 8) * EMB + c) =
                    make_float2(acc[mi][ni][2] + bv0, acc[mi][ni][3] + bv1);
            }
        }
    }
}

// ---------------------------------------------------------------------------
// Plain-fp16 flash attention, log2-domain softmax (EX2 only), conditional
// rescale. Br=64, cp.async double-buffer, ldmatrix, occ 4.
// ---------------------------------------------------------------------------
#define ASTR 72
#define A_STG (64 * ASTR)
#define ATT_SMEM (4 * A_STG * 2)           // 36864 B

__global__ void __launch_bounds__(128, 4)
attn_mma_kernel(const __half* __restrict__ Qh,
                const __half* __restrict__ Kh,
                const __half* __restrict__ VTh,
                __half* __restrict__ Out)
{
    extern __shared__ __half sm[];
    __half* sK  = sm;
    __half* sVT = sm + 2 * A_STG;

    const int tid  = threadIdx.x;
    const int wid  = tid >> 5;
    const int lane = tid & 31;
    const int g    = lane >> 2;
    const int t    = lane & 3;
    const int qt   = blockIdx.x;
    const int bh   = blockIdx.y;
    const size_t base  = (size_t)bh * SEQ * HDIM;
    const size_t baseT = (size_t)bh * HDIM * SEQ;

    const int brow = (lane & 7) + ((lane >> 4) & 1) * 8;
    const int bcol = ((lane >> 3) & 1) * 8;

#pragma unroll
    for (int i = 0; i < 4; i++) {
        int idx = tid + 128 * i;
        int row = idx >> 3;
        int co  = (idx & 7) * 8;
        *(uint4*)&sK[row * ASTR + co] = *(const uint4*)&Qh[base + (size_t)(qt * 64 + row) * HDIM + co];
    }
    __syncthreads();

    uint32_t qh[4][4];
    {
        const int arow = (lane & 7) + ((lane >> 3) & 1) * 8;
        const int acol = (lane >> 4) * 8;
        const uint32_t qBase = smem_u32(sK);
#pragma unroll
        for (int kj = 0; kj < 4; kj++) {
            uint32_t ah = qBase + (((uint32_t)(wid * 16 + arow)) * ASTR + 16 * kj + acol) * 2;
            ldsm_x4(qh[kj][0], qh[kj][1], qh[kj][2], qh[kj][3], ah);
        }
    }
    __syncthreads();

    const uint32_t sKa  = smem_u32(sK);
    const uint32_t sVTa = smem_u32(sVT);
    auto stage = [&](int st, int kt) {
#pragma unroll
        for (int j = 0; j < 4; j++) {
            int id  = tid + 128 * j;
            int row = id >> 3;
            int co  = (id & 7) * 8;
            uint32_t so = ((uint32_t)row * ASTR + co) * 2;
            CP_ASYNC16(sKa  + st * A_STG * 2 + so, Kh  + base  + (size_t)(kt + row) * HDIM + co);
            CP_ASYNC16(sVTa + st * A_STG * 2 + so, VTh + baseT + (size_t)row * SEQ + kt + co);
        }
        CP_COMMIT();
    };

    float o[8][4];
#pragma unroll
    for (int ni = 0; ni < 8; ni++)
#pragma unroll
        for (int j = 0; j < 4; j++) o[ni][j] = 0.f;
    float m0 = -1e30f, m1 = -1e30f, l0 = 0.f, l1 = 0.f;

    stage(0, 0);
    stage(1, 64);

    const int NT = SEQ / 64;
    for (int it = 0; it < NT; it++) {
        const int s = it & 1;
        if (it + 1 < NT) { CP_WAIT1(); } else { CP_WAIT0(); }
        __syncthreads();

        const uint32_t cKA = sKa  + s * A_STG * 2;
        const uint32_t cVA = sVTa + s * A_STG * 2;
        const uint32_t bOff = ((uint32_t)brow * ASTR + bcol) * 2;

        // --- S' = Q K^T (log2 domain) ---
        float sc[8][4];
#pragma unroll
        for (int ni = 0; ni < 8; ni++)
#pragma unroll
            for (int j = 0; j < 4; j++) sc[ni][j] = 0.f;

#pragma unroll
        for (int kj = 0; kj < 4; kj++) {
#pragma unroll
            for (int np = 0; np < 4; np++) {
                uint32_t off = bOff + ((uint32_t)np * 16 * ASTR + 16 * kj) * 2;
                uint32_t h0[2], h1[2];
                ldsm_x4(h0[0], h0[1], h1[0], h1[1], cKA + off);
                mma16816(sc[2 * np],     qh[kj], h0);
                mma16816(sc[2 * np + 1], qh[kj], h1);
            }
        }

        // --- online softmax (EX2, conditional rescale) ---
        float mx0 = -1e30f, mx1 = -1e30f;
#pragma unroll
        for (int ni = 0; ni < 8; ni++) {
            mx0 = fmaxf(mx0, fmaxf(sc[ni][0], sc[ni][1]));
            mx1 = fmaxf(mx1, fmaxf(sc[ni][2], sc[ni][3]));
        }
        mx0 = fmaxf(mx0, __shfl_xor_sync(0xffffffff, mx0, 1));
        mx0 = fmaxf(mx0, __shfl_xor_sync(0xffffffff, mx0, 2));
        mx1 = fmaxf(mx1, __shfl_xor_sync(0xffffffff, mx1, 1));
        mx1 = fmaxf(mx1, __shfl_xor_sync(0xffffffff, mx1, 2));

        const float nm0 = fmaxf(m0, mx0);
        const float nm1 = fmaxf(m1, mx1);
        const bool upd = (nm0 != m0) || (nm1 != m1);
        if (__any_sync(0xffffffff, upd)) {
            const float rs0 = ex2f(m0 - nm0);
            const float rs1 = ex2f(m1 - nm1);
            l0 *= rs0; l1 *= rs1;
#pragma unroll
            for (int ni = 0; ni < 8; ni++) {
                o[ni][0] *= rs0; o[ni][1] *= rs0;
                o[ni][2] *= rs1; o[ni][3] *= rs1;
            }
            m0 = nm0; m1 = nm1;
        }
#pragma unroll
        for (int ni = 0; ni < 8; ni++) {
            sc[ni][0] = ex2f(sc[ni][0] - m0);
            sc[ni][1] = ex2f(sc[ni][1] - m0);
            sc[ni][2] = ex2f(sc[ni][2] - m1);
            sc[ni][3] = ex2f(sc[ni][3] - m1);
            l0 += sc[ni][0] + sc[ni][1];
            l1 += sc[ni][2] + sc[ni][3];
        }

        // --- O += P V ---
#pragma unroll
        for (int kj = 0; kj < 4; kj++) {
            uint32_t ah[4];
            ah[0] = packh2(sc[2 * kj][0],     sc[2 * kj][1]);
            ah[1] = packh2(sc[2 * kj][2],     sc[2 * kj][3]);
            ah[2] = packh2(sc[2 * kj + 1][0], sc[2 * kj + 1][1]);
            ah[3] = packh2(sc[2 * kj + 1][2], sc[2 * kj + 1][3]);
#pragma unroll
            for (int np = 0; np < 4; np++) {
                uint32_t off = bOff + ((uint32_t)np * 16 * ASTR + 16 * kj) * 2;
                uint32_t h0[2], h1[2];
                ldsm_x4(h0[0], h0[1], h1[0], h1[1], cVA + off);
                mma16816(o[2 * np],     ah, h0);
                mma16816(o[2 * np + 1], ah, h1);
            }
        }

        __syncthreads();
        if (it + 2 < NT) stage(s, (it + 2) * 64);
    }

    // --- finalize ---
    l0 += __shfl_xor_sync(0xffffffff, l0, 1);
    l0 += __shfl_xor_sync(0xffffffff, l0, 2);
    l1 += __shfl_xor_sync(0xffffffff, l1, 1);
    l1 += __shfl_xor_sync(0xffffffff, l1, 2);
    const float inv0 = 1.f / l0;
    const float inv1 = 1.f / l1;

    const int s0 = qt * 64 + wid * 16 + g;
    const int b  = bh >> 4;
    const int h  = bh & 15;
    const size_t row0 = (size_t)(b * SEQ + s0) * KG;
    const size_t row1 = row0 + (size_t)8 * KG;

#pragma unroll
    for (int ni = 0; ni < 8; ni++) {
        const int col = h * 64 + 8 * ni + 2 * t;
        *(uint32_t*)&Out[row0 + col] = packh2(o[ni][0] * inv0, o[ni][1] * inv0);
        *(uint32_t*)&Out[row1 + col] = packh2(o[ni][2] * inv1, o[ni][3] * inv1);
    }
}

// ---------------------------------------------------------------------------
extern "C" void kernel_launch(void* const* d_in, const int* in_sizes, int n_in,
                              void* d_out, int out_size)
{
    const float* X   = (const float*)d_in[0];
    const float* W_q = (const float*)d_in[1];
    const float* b_q = (const float*)d_in[2];
    const float* W_k = (const float*)d_in[3];
    const float* b_k = (const float*)d_in[4];
    const float* W_v = (const float*)d_in[5];
    const float* b_v = (const float*)d_in[6];
    const float* W_o = (const float*)d_in[7];
    const float* b_o = (const float*)d_in[8];
    float* out = (float*)d_out;

    __half *Qh, *Kh, *VTh, *Xs, *Ws, *As;
    cudaGetSymbolAddress((void**)&Qh, g_Qh);
    cudaGetSymbolAddress((void**)&Kh, g_Kh);
    cudaGetSymbolAddress((void**)&VTh, g_VTh);
    cudaGetSymbolAddress((void**)&Xs, g_Xs);
    cudaGetSymbolAddress((void**)&Ws, g_Ws);
    cudaGetSymbolAddress((void**)&As, g_As);

    cudaFuncSetAttribute(gemm_mma_kernel, cudaFuncAttributeMaxDynamicSharedMemorySize, G_SMEM);
    cudaFuncSetAttribute(attn_mma_kernel, cudaFuncAttributeMaxDynamicSharedMemorySize, ATT_SMEM);

    const int cthr = 256;
    // fused conversions: y=0 covers X (4M elems), y=1..4 the four weights (1M each)
    dim3 cgrid(MROWS * EMB / (cthr * 4), 5);
    conv_kernel<<<cgrid, cthr>>>(X, W_q, W_k, W_v, W_o, Xs, Ws);

    // fused QKV: N = 3072, tile 128x128, K = 1024
    dim3 qkvgrid(3 * EMB / 128, MROWS / 128);   // (24, 32)
    gemm_mma_kernel<<<qkvgrid, 256, G_SMEM>>>(Xs, Ws, b_q, b_k, b_v,
                                              Qh, Kh, VTh, nullptr, 0);

    dim3 agrid(SEQ / 64, BATCH * NHEAD);
    attn_mma_kernel<<<agrid, 128, ATT_SMEM>>>(Qh, Kh, VTh, As);

    // O-projection: N = 1024, K = 1024
    dim3 ogrid(EMB / 128, MROWS / 128);    // (8, 32)
    gemm_mma_kernel<<<ogrid, 256, G_SMEM>>>(As, Ws + 3 * (size_t)EMB * KG, b_o, nullptr, nullptr,
                                            nullptr, nullptr, nullptr,
                                            out, 1);
}